// round 10
// baseline (speedup 1.0000x reference)
#include <cuda_runtime.h>
#include <cuda_bf16.h>
#include <math.h>
#include <stdint.h>

#define SEQ   2048
#define BATCH 2
#define DIM   1024
#define HEADS 16
#define DKH   64
#define NROW  (SEQ*BATCH)   // 4096
#define BH    (BATCH*HEADS) // 32

typedef unsigned long long u64;

// ---------------- mma.sync helpers (portable sm_80+ ISA) ----------------
__device__ __forceinline__ uint32_t smem_to_u32(const void* p) {
    uint32_t a;
    asm("{ .reg .u64 t; cvta.to.shared.u64 t, %1; cvt.u32.u64 %0, t; }" : "=r"(a) : "l"(p));
    return a;
}
__device__ __forceinline__ void cpasync16(uint32_t s, const void* g) {
    asm volatile("cp.async.cg.shared.global [%0], [%1], 16;" :: "r"(s), "l"(g) : "memory");
}
__device__ __forceinline__ void ldsm4(uint32_t* r, uint32_t addr) {
    asm volatile("ldmatrix.sync.aligned.m8n8.x4.shared.b16 {%0,%1,%2,%3}, [%4];"
        : "=r"(r[0]), "=r"(r[1]), "=r"(r[2]), "=r"(r[3]) : "r"(addr));
}
__device__ __forceinline__ void mma16816(float* d, const uint32_t* a, const uint32_t* b) {
    asm volatile("mma.sync.aligned.m16n8k16.row.col.f32.bf16.bf16.f32 "
        "{%0,%1,%2,%3}, {%4,%5,%6,%7}, {%8,%9}, {%0,%1,%2,%3};"
        : "+f"(d[0]), "+f"(d[1]), "+f"(d[2]), "+f"(d[3])
        : "r"(a[0]), "r"(a[1]), "r"(a[2]), "r"(a[3]), "r"(b[0]), "r"(b[1]));
}
// pack (lo=a, hi=b) into bf16x2
__device__ __forceinline__ uint32_t pack2(float lo, float hi) {
    uint32_t r; asm("cvt.rn.bf16x2.f32 %0, %1, %2;" : "=r"(r) : "f"(hi), "f"(lo)); return r;
}

#define SWZ(row, c16) ((row)*128 + ((((c16) ^ ((row)&7)))<<4))

// ---------------- scratch (device globals; no allocation allowed) ----------------
__device__ float g_qx[NROW*DIM];
__device__ float g_kx[NROW*DIM];
__device__ float g_vx[NROW*DIM];
__device__ float g_qc[NROW*DIM];
__device__ float g_kc[NROW*DIM];
__device__ float g_ctx[NROW*DIM];
__device__ __nv_bfloat16 g_sA[5*2*NROW*DIM];
__device__ __nv_bfloat16 g_sW[6*2*DIM*DIM];
__device__ __nv_bfloat16 g_sC[2*NROW*DIM];
__device__ __nv_bfloat16 g_qh[BH*SEQ*DKH];
__device__ __nv_bfloat16 g_ql[BH*SEQ*DKH];
__device__ __nv_bfloat16 g_kh[BH*SEQ*DKH];
__device__ __nv_bfloat16 g_kl[BH*SEQ*DKH];
__device__ __nv_bfloat16 g_vth[BH*DKH*SEQ];
__device__ __nv_bfloat16 g_vtl[BH*DKH*SEQ];

// ================= split2: fp32 -> bf16 hi/lo planes =================
__global__ __launch_bounds__(256)
void split2_kernel(const float4* __restrict__ in, __nv_bfloat16* __restrict__ o1,
                   __nv_bfloat16* __restrict__ o2, int n4) {
    int i = blockIdx.x * blockDim.x + threadIdx.x;
    if (i >= n4) return;
    float4 v = in[i];
    float vv[4] = {v.x, v.y, v.z, v.w};
    union { __nv_bfloat16 h[4]; uint2 u; } p1, p2;
#pragma unroll
    for (int k = 0; k < 4; k++) {
        __nv_bfloat16 a1 = __float2bfloat16(vv[k]);
        float r  = vv[k] - __bfloat162float(a1);
        p1.h[k] = a1; p2.h[k] = __float2bfloat16(r);
    }
    *(uint2*)(o1 + 4*(size_t)i) = p1.u;
    *(uint2*)(o2 + 4*(size_t)i) = p2.u;
}

// ================= weight transpose + split =================
struct WArg  { const float* W; __nv_bfloat16 *o1, *o2; };
struct WArgs { WArg w[6]; };
__global__ __launch_bounds__(256)
void wsplit_kernel(WArgs a) {
    __shared__ float tile[32][33];
    WArg wa = a.w[blockIdx.z];
    int tx = threadIdx.x, ty = threadIdx.y;
    int x = blockIdx.x * 32 + tx;
    int yb = blockIdx.y * 32;
#pragma unroll
    for (int j = 0; j < 32; j += 8)
        tile[ty + j][tx] = wa.W[(size_t)(yb + ty + j) * DIM + x];
    __syncthreads();
    int xo = blockIdx.y * 32 + tx;
    int yo = blockIdx.x * 32;
#pragma unroll
    for (int j = 0; j < 32; j += 8) {
        float v = tile[tx][ty + j];
        size_t o = (size_t)(yo + ty + j) * DIM + xo;
        __nv_bfloat16 b1 = __float2bfloat16(v);
        float r  = v - __bfloat162float(b1);
        wa.o1[o] = b1; wa.o2[o] = __float2bfloat16(r);
    }
}

// ================= HMMA bf16x2 GEMM v3: 256x128 tile, warp tile 64x64 =================
// Per stage: A1|A2 (32KB each, 256 rows x 128B) and B1|B2 (16KB each).
// 2-stage double buffer. Per kstep per warp: 16 LDSM.x4 -> 96 MMA (6:1).
#define GBK 64
#define A_TILE_B 32768
#define B_TILE_B 16384
#define GSTAGE_B (2*A_TILE_B + 2*B_TILE_B)   // 98304
#define GEMM_SMEM (2*GSTAGE_B)               // 196608
#define GNCH 16

struct GArg  { const __nv_bfloat16* A[2]; const __nv_bfloat16* B[2]; const float* bias; float* C; };
struct GArgs { GArg g[5]; };

__global__ __launch_bounds__(256, 1)
void gemm_mma_kernel(GArgs args) {
    extern __shared__ char smem[];
    const uint32_t sb = smem_to_u32(smem);
    GArg ga = args.g[blockIdx.z];
    const int t = threadIdx.x;
    const int wid = t >> 5, lane = t & 31;
    const int wm = wid & 3, wn = wid >> 2;      // 4 x 2 warps, warp tile 64x64
    const int m0 = blockIdx.y * 256, n0 = blockIdx.x * 128;

    float acc[4][8][4];
#pragma unroll
    for (int i = 0; i < 4; i++)
#pragma unroll
        for (int j = 0; j < 8; j++)
#pragma unroll
            for (int k = 0; k < 4; k++) acc[i][j][k] = 0.f;

    auto issue = [&](int c) {
        const int kc = c * GBK;
        const uint32_t st = sb + (c & 1) * GSTAGE_B;
        // A planes: 256 rows x 8 c16 each
#pragma unroll
        for (int p = 0; p < 2; p++) {
            const __nv_bfloat16* base = ga.A[p];
            const uint32_t tb = st + p * A_TILE_B;
#pragma unroll
            for (int i = 0; i < 8; i++) {
                int e = i * 256 + t;
                int c16 = e & 7, row = e >> 3;
                cpasync16(tb + SWZ(row, c16),
                          base + (size_t)(m0 + row) * DIM + kc + c16 * 8);
            }
        }
        // B planes: 128 rows x 8 c16 each
#pragma unroll
        for (int p = 0; p < 2; p++) {
            const __nv_bfloat16* base = ga.B[p];
            const uint32_t tb = st + 2 * A_TILE_B + p * B_TILE_B;
#pragma unroll
            for (int i = 0; i < 4; i++) {
                int e = i * 256 + t;
                int c16 = e & 7, row = e >> 3;
                cpasync16(tb + SWZ(row, c16),
                          base + (size_t)(n0 + row) * DIM + kc + c16 * 8);
            }
        }
        asm volatile("cp.async.commit_group;" ::: "memory");
    };

    issue(0); issue(1);

    for (int c = 0; c < GNCH; c++) {
        if (c + 1 < GNCH) {
            asm volatile("cp.async.wait_group 1;" ::: "memory");
        } else {
            asm volatile("cp.async.wait_group 0;" ::: "memory");
        }
        __syncthreads();

        const uint32_t st = sb + (c & 1) * GSTAGE_B;
        const uint32_t A1 = st, A2 = st + A_TILE_B;
        const uint32_t B1 = st + 2*A_TILE_B, B2 = B1 + B_TILE_B;
#pragma unroll
        for (int ks = 0; ks < 4; ks++) {
            uint32_t af1[4][4], af2[4][4];
            {
                int arb = wm*64 + (lane & 15);
                int ac16 = ks*2 + ((lane >> 4) & 1);
#pragma unroll
                for (int tm = 0; tm < 4; tm++) {
                    ldsm4(af1[tm], A1 + SWZ(arb + tm*16, ac16));
                    ldsm4(af2[tm], A2 + SWZ(arb + tm*16, ac16));
                }
            }
            int br = (lane & 7) + ((lane >> 4) & 1) * 8;
            int bc16 = ks*2 + ((lane >> 3) & 1);
#pragma unroll
            for (int g = 0; g < 4; g++) {
                uint32_t bb1[4], bb2[4];
                int rr = wn*64 + g*16 + br;
                ldsm4(bb1, B1 + SWZ(rr, bc16));
                ldsm4(bb2, B2 + SWZ(rr, bc16));
#pragma unroll
                for (int tm = 0; tm < 4; tm++) {
#pragma unroll
                    for (int h = 0; h < 2; h++) {
                        float* ac = acc[tm][g*2 + h];
                        mma16816(ac, af1[tm], &bb1[h*2]);
                        mma16816(ac, af2[tm], &bb1[h*2]);
                        mma16816(ac, af1[tm], &bb2[h*2]);
                    }
                }
            }
        }
        __syncthreads();
        if (c + 2 < GNCH) issue(c + 2);
    }

    // epilogue: fragment layout -> C + bias (float2 stores)
#pragma unroll
    for (int tm = 0; tm < 4; tm++) {
        int r0 = m0 + wm*64 + tm*16 + lane / 4;
#pragma unroll
        for (int tn = 0; tn < 8; tn++) {
            int cc = n0 + wn*64 + tn*8 + (lane % 4) * 2;
            float2 bv = *(const float2*)&ga.bias[cc];
            float2 v0 = make_float2(acc[tm][tn][0] + bv.x, acc[tm][tn][1] + bv.y);
            float2 v1 = make_float2(acc[tm][tn][2] + bv.x, acc[tm][tn][3] + bv.y);
            *(float2*)&ga.C[(size_t)r0 * DIM + cc] = v0;
            *(float2*)&ga.C[(size_t)(r0 + 8) * DIM + cc] = v1;
        }
    }
}

// ---------------- lambda gate + mix -> bf16 planes [bh][s][dk] ----------------
__global__ __launch_bounds__(256)
void lam_mix_kernel(const float* __restrict__ Wvqx, const float* __restrict__ bvqx,
                    const float* __restrict__ Wvqc, const float* __restrict__ bvqc,
                    const float* __restrict__ Wvkx, const float* __restrict__ bvkx,
                    const float* __restrict__ Wvkc, const float* __restrict__ bvkc) {
    const int r   = blockIdx.x;
    const bool isK = (blockIdx.y != 0);
    const float* a = isK ? g_kx : g_qx;
    const float* c = isK ? g_kc : g_qc;
    const float* Wa = isK ? Wvkx : Wvqx;
    const float* Wc = isK ? Wvkc : Wvqc;
    const float bsum = isK ? (bvkx[0] + bvkc[0]) : (bvqx[0] + bvqc[0]);
    __nv_bfloat16* oh = isK ? g_kh : g_qh;
    __nv_bfloat16* ol = isK ? g_kl : g_ql;

    const int t = threadIdx.x;
    const int s = r >> 1, b = r & 1;
    float av[4], cv[4];
    float part = 0.f;
#pragma unroll
    for (int i = 0; i < 4; i++) {
        int d = t + i*256;
        av[i] = a[(size_t)r*1024 + d];
        cv[i] = c[(size_t)r*1024 + d];
        part += av[i]*Wa[d] + cv[i]*Wc[d];
    }
    __shared__ float red[256];
    red[t] = part;
    __syncthreads();
    for (int ss = 128; ss > 0; ss >>= 1) {
        if (t < ss) red[t] += red[t+ss];
        __syncthreads();
    }
    float lam = 1.f / (1.f + __expf(-(red[0] + bsum)));
#pragma unroll
    for (int i = 0; i < 4; i++) {
        int d = t + i*256;
        float m = av[i] + lam*(cv[i] - av[i]);
        int hh = d >> 6, dk = d & 63;
        size_t off = ((size_t)(b*HEADS + hh)*SEQ + s)*DKH + dk;
        __nv_bfloat16 mh = __float2bfloat16(m);
        oh[off] = mh;
        ol[off] = __float2bfloat16(m - __bfloat162float(mh));
    }
}

// ---------------- V transpose + split: g_vx -> Vt planes [bh][dk][s] ----------------
__global__ __launch_bounds__(256)
void vsplit_kernel() {
    __shared__ float tile[64][65];
    const int t = threadIdx.x;
    const int s0 = blockIdx.x * 64, bh = blockIdx.y;
    const int b = bh >> 4, h = bh & 15;
#pragma unroll
    for (int i = 0; i < 4; i++) {
        int e = i*256 + t;
        int sr = e >> 4, c4 = e & 15;
        float4 v = *(const float4*)&g_vx[((size_t)(s0+sr)*BATCH + b)*DIM + h*DKH + c4*4];
        tile[sr][c4*4+0] = v.x; tile[sr][c4*4+1] = v.y;
        tile[sr][c4*4+2] = v.z; tile[sr][c4*4+3] = v.w;
    }
    __syncthreads();
    const int dkr = t >> 2, sc = (t & 3) * 16;
    union { __nv_bfloat16 h[8]; uint4 u; } hp[2], lp[2];
#pragma unroll
    for (int ch = 0; ch < 2; ch++)
#pragma unroll
        for (int k = 0; k < 8; k++) {
            float v = tile[sc + ch*8 + k][dkr];
            __nv_bfloat16 hb = __float2bfloat16(v);
            hp[ch].h[k] = hb;
            lp[ch].h[k] = __float2bfloat16(v - __bfloat162float(hb));
        }
    size_t off = ((size_t)bh*DKH + dkr)*SEQ + s0 + sc;
    *(uint4*)&g_vth[off] = hp[0].u; *(uint4*)&g_vth[off+8] = hp[1].u;
    *(uint4*)&g_vtl[off] = lp[0].u; *(uint4*)&g_vtl[off+8] = lp[1].u;
}

// ---------------- HMMA flash attention ----------------
#define FL_SMEM (32768 + 2*32768)

__global__ __launch_bounds__(256)
void flash_mma_kernel() {
    extern __shared__ char fsm[];
    const uint32_t sb = smem_to_u32(fsm);
    const int t = threadIdx.x, lane = t & 31, w = t >> 5;
    const int q0 = blockIdx.x * 128, bh = blockIdx.y;
    const int row0 = w * 16;

    {
        size_t qoff = ((size_t)bh*SEQ + q0)*DKH;
#pragma unroll
        for (int i = 0; i < 8; i++) {
            int e = i*256 + t;
            int c16 = e & 7, row = (e >> 3) & 127, pl = e >> 10;
            const __nv_bfloat16* src = (pl ? g_ql : g_qh) + qoff + row*DKH + c16*8;
            cpasync16(sb + pl*16384 + SWZ(row, c16), src);
        }
        asm volatile("cp.async.commit_group;" ::: "memory");
    }
    auto issue_kv = [&](int kt, int st) {
        int k0 = kt * 64;
#pragma unroll
        for (int i = 0; i < 8; i++) {
            int e = i*256 + t;
            int c16 = e & 7, row = (e >> 3) & 63, pl = e >> 9;
            const __nv_bfloat16* src;
            if (pl < 2) src = (pl ? g_kl : g_kh) + ((size_t)bh*SEQ + k0 + row)*DKH + c16*8;
            else src = (pl == 3 ? g_vtl : g_vth) + ((size_t)bh*DKH + row)*SEQ + k0 + c16*8;
            cpasync16(sb + 32768 + st*32768 + pl*8192 + SWZ(row, c16), src);
        }
        asm volatile("cp.async.commit_group;" ::: "memory");
    };
    issue_kv(0, 0);

    float m0r = -1e30f, m1r = -1e30f, l0 = 0.f, l1 = 0.f;
    float oacc[8][4];
#pragma unroll
    for (int j = 0; j < 8; j++)
#pragma unroll
        for (int k = 0; k < 4; k++) oacc[j][k] = 0.f;

    for (int kt = 0; kt < 32; kt++) {
        const int st = kt & 1;
        if (kt + 1 < 32) {
            issue_kv(kt + 1, st ^ 1);
            asm volatile("cp.async.wait_group 1;" ::: "memory");
        } else {
            asm volatile("cp.async.wait_group 0;" ::: "memory");
        }
        __syncthreads();

        const uint32_t Kh = sb + 32768 + st*32768;
        const uint32_t Kl = Kh + 8192, Vh = Kh + 16384, Vl = Kh + 24576;

        float sacc[8][4];
#pragma unroll
        for (int j = 0; j < 8; j++)
#pragma unroll
            for (int k = 0; k < 4; k++) sacc[j][k] = 0.f;

#pragma unroll
        for (int ks = 0; ks < 4; ks++) {
            uint32_t a1[4], a2[4];
            {
                int r = row0 + (lane & 15);
                int c16 = ks*2 + ((lane >> 4) & 1);
                ldsm4(a1, sb + SWZ(r, c16));
                ldsm4(a2, sb + 16384 + SWZ(r, c16));
            }
            uint32_t bb[4][4];
            int br = (lane & 7) + ((lane >> 4) & 1) * 8;
            int bc16 = ks*2 + ((lane >> 3) & 1);
#pragma unroll
            for (int g = 0; g < 4; g++) { int rr = g*16 + br; ldsm4(bb[g], Kh + SWZ(rr, bc16)); }
#pragma unroll
            for (int j = 0; j < 8; j++) mma16816(sacc[j], a1, &bb[j>>1][(j&1)*2]);
#pragma unroll
            for (int j = 0; j < 8; j++) mma16816(sacc[j], a2, &bb[j>>1][(j&1)*2]);
#pragma unroll
            for (int g = 0; g < 4; g++) { int rr = g*16 + br; ldsm4(bb[g], Kl + SWZ(rr, bc16)); }
#pragma unroll
            for (int j = 0; j < 8; j++) mma16816(sacc[j], a1, &bb[j>>1][(j&1)*2]);
        }

        float mx0 = -1e30f, mx1 = -1e30f;
#pragma unroll
        for (int j = 0; j < 8; j++) {
#pragma unroll
            for (int k = 0; k < 4; k++) sacc[j][k] *= 0.125f;
            mx0 = fmaxf(mx0, fmaxf(sacc[j][0], sacc[j][1]));
            mx1 = fmaxf(mx1, fmaxf(sacc[j][2], sacc[j][3]));
        }
        mx0 = fmaxf(mx0, __shfl_xor_sync(0xffffffffu, mx0, 1));
        mx0 = fmaxf(mx0, __shfl_xor_sync(0xffffffffu, mx0, 2));
        mx1 = fmaxf(mx1, __shfl_xor_sync(0xffffffffu, mx1, 1));
        mx1 = fmaxf(mx1, __shfl_xor_sync(0xffffffffu, mx1, 2));
        float mn0 = fmaxf(m0r, mx0), mn1 = fmaxf(m1r, mx1);
        float corr0 = __expf(m0r - mn0), corr1 = __expf(m1r - mn1);
        m0r = mn0; m1r = mn1;
        float rs0 = 0.f, rs1 = 0.f;
#pragma unroll
        for (int j = 0; j < 8; j++) {
            sacc[j][0] = __expf(sacc[j][0] - mn0);
            sacc[j][1] = __expf(sacc[j][1] - mn0);
            sacc[j][2] = __expf(sacc[j][2] - mn1);
            sacc[j][3] = __expf(sacc[j][3] - mn1);
            rs0 += sacc[j][0] + sacc[j][1];
            rs1 += sacc[j][2] + sacc[j][3];
            oacc[j][0] *= corr0; oacc[j][1] *= corr0;
            oacc[j][2] *= corr1; oacc[j][3] *= corr1;
        }
        rs0 += __shfl_xor_sync(0xffffffffu, rs0, 1);
        rs0 += __shfl_xor_sync(0xffffffffu, rs0, 2);
        rs1 += __shfl_xor_sync(0xffffffffu, rs1, 1);
        rs1 += __shfl_xor_sync(0xffffffffu, rs1, 2);
        l0 = l0*corr0 + rs0;
        l1 = l1*corr1 + rs1;

        uint32_t ph[4][4], pl[4][4];
#pragma unroll
        for (int ks = 0; ks < 4; ks++) {
            int j0 = 2*ks, j1 = 2*ks + 1;
            float p00 = sacc[j0][0], p01 = sacc[j0][1], p02 = sacc[j0][2], p03 = sacc[j0][3];
            float p10 = sacc[j1][0], p11 = sacc[j1][1], p12 = sacc[j1][2], p13 = sacc[j1][3];
            uint32_t h0 = pack2(p00, p01), h1 = pack2(p02, p03);
            uint32_t h2 = pack2(p10, p11), h3 = pack2(p12, p13);
            ph[ks][0] = h0; ph[ks][1] = h1; ph[ks][2] = h2; ph[ks][3] = h3;
            pl[ks][0] = pack2(p00 - __uint_as_float(h0 << 16), p01 - __uint_as_float(h0 & 0xffff0000u));
            pl[ks][1] = pack2(p02 - __uint_as_float(h1 << 16), p03 - __uint_as_float(h1 & 0xffff0000u));
            pl[ks][2] = pack2(p10 - __uint_as_float(h2 << 16), p11 - __uint_as_float(h2 & 0xffff0000u));
            pl[ks][3] = pack2(p12 - __uint_as_float(h3 << 16), p13 - __uint_as_float(h3 & 0xffff0000u));
        }

#pragma unroll
        for (int ks = 0; ks < 4; ks++) {
            uint32_t bb[4][4];
            int br = (lane & 7) + ((lane >> 4) & 1) * 8;
            int bc16 = ks*2 + ((lane >> 3) & 1);
#pragma unroll
            for (int g = 0; g < 4; g++) { int rr = g*16 + br; ldsm4(bb[g], Vh + SWZ(rr, bc16)); }
#pragma unroll
            for (int j = 0; j < 8; j++) mma16816(oacc[j], ph[ks], &bb[j>>1][(j&1)*2]);
#pragma unroll
            for (int j = 0; j < 8; j++) mma16816(oacc[j], pl[ks], &bb[j>>1][(j&1)*2]);
#pragma unroll
            for (int g = 0; g < 4; g++) { int rr = g*16 + br; ldsm4(bb[g], Vl + SWZ(rr, bc16)); }
#pragma unroll
            for (int j = 0; j < 8; j++) mma16816(oacc[j], ph[ks], &bb[j>>1][(j&1)*2]);
        }
        __syncthreads();
    }

    const float inv0 = 1.f / l0, inv1 = 1.f / l1;
    const int b = bh >> 4, h = bh & 15;
    const int sg = q0 + row0 + (lane >> 2);
#pragma unroll
    for (int j = 0; j < 8; j++) {
        int dk = j*8 + (lane & 3)*2;
        float2 v0 = make_float2(oacc[j][0]*inv0, oacc[j][1]*inv0);
        float2 v1 = make_float2(oacc[j][2]*inv1, oacc[j][3]*inv1);
        *(float2*)&g_ctx[((size_t)sg*BATCH + b)*DIM + h*DKH + dk] = v0;
        *(float2*)&g_ctx[((size_t)(sg+8)*BATCH + b)*DIM + h*DKH + dk] = v1;
    }
}

// ---------------- launch ----------------
extern "C" void kernel_launch(void* const* d_in, const int* in_sizes, int n_in,
                              void* d_out, int out_size) {
    const float* in5[5]  = {(const float*)d_in[0], (const float*)d_in[1], (const float*)d_in[2],
                            (const float*)d_in[3], (const float*)d_in[4]};
    const float* W6[6]   = {(const float*)d_in[5],  (const float*)d_in[7],  (const float*)d_in[9],
                            (const float*)d_in[11], (const float*)d_in[13], (const float*)d_in[15]};
    const float* bias6[6]= {(const float*)d_in[6],  (const float*)d_in[8],  (const float*)d_in[10],
                            (const float*)d_in[12], (const float*)d_in[14], (const float*)d_in[16]};
    const float* W_Vqx= (const float*)d_in[17];
    const float* b_Vqx= (const float*)d_in[18];
    const float* W_Vqc= (const float*)d_in[19];
    const float* b_Vqc= (const float*)d_in[20];
    const float* W_Vkx= (const float*)d_in[21];
    const float* b_Vkx= (const float*)d_in[22];
    const float* W_Vkc= (const float*)d_in[23];
    const float* b_Vkc= (const float*)d_in[24];

    float *p_out5[5], *p_ctx;
    cudaGetSymbolAddress((void**)&p_out5[0], g_qx);
    cudaGetSymbolAddress((void**)&p_out5[1], g_kx);
    cudaGetSymbolAddress((void**)&p_out5[2], g_vx);
    cudaGetSymbolAddress((void**)&p_out5[3], g_qc);
    cudaGetSymbolAddress((void**)&p_out5[4], g_kc);
    cudaGetSymbolAddress((void**)&p_ctx,     g_ctx);
    __nv_bfloat16 *pA, *pW, *pC;
    cudaGetSymbolAddress((void**)&pA, g_sA);
    cudaGetSymbolAddress((void**)&pW, g_sW);
    cudaGetSymbolAddress((void**)&pC, g_sC);

    const size_t NA = (size_t)NROW * DIM;
    const size_t NW = (size_t)DIM * DIM;
    const int n4 = (int)(NA / 4);

    // 1) split inputs into bf16 hi/lo planes
    for (int i = 0; i < 5; i++)
        split2_kernel<<<n4/256, 256>>>((const float4*)in5[i],
                                       pA + (size_t)(i*2+0)*NA,
                                       pA + (size_t)(i*2+1)*NA, n4);

    // 2) transpose + split weights
    WArgs wa;
    for (int i = 0; i < 6; i++)
        wa.w[i] = { W6[i], pW + (size_t)(i*2+0)*NW, pW + (size_t)(i*2+1)*NW };
    wsplit_kernel<<<dim3(32, 32, 6), dim3(32, 8)>>>(wa);

    // 3) five projections on HMMA tensor cores (256x128 tiles)
    cudaFuncSetAttribute(gemm_mma_kernel, cudaFuncAttributeMaxDynamicSharedMemorySize, GEMM_SMEM);
    GArgs ga;
    for (int i = 0; i < 5; i++) {
        GArg g;
        for (int p = 0; p < 2; p++) {
            g.A[p] = pA + (size_t)(i*2+p)*NA;
            g.B[p] = pW + (size_t)(i*2+p)*NW;
        }
        g.bias = bias6[i];
        g.C = p_out5[i];
        ga.g[i] = g;
    }
    gemm_mma_kernel<<<dim3(8, 16, 5), 256, GEMM_SMEM>>>(ga);

    // 4) lambda gates + mixing -> bf16 planes; V transpose+split
    lam_mix_kernel<<<dim3(NROW, 2), 256>>>(W_Vqx, b_Vqx, W_Vqc, b_Vqc,
                                           W_Vkx, b_Vkx, W_Vkc, b_Vkc);
    vsplit_kernel<<<dim3(SEQ/64, BH), 256>>>();

    // 5) HMMA flash attention
    cudaFuncSetAttribute(flash_mma_kernel, cudaFuncAttributeMaxDynamicSharedMemorySize, FL_SMEM);
    flash_mma_kernel<<<dim3(SEQ/128, BH), 256, FL_SMEM>>>();

    // 6) split ctx, then output projection into d_out
    split2_kernel<<<n4/256, 256>>>((const float4*)p_ctx, pC, pC + NA, n4);
    GArgs go;
    {
        GArg g;
        for (int p = 0; p < 2; p++) {
            g.A[p] = pC + (size_t)p*NA;
            g.B[p] = pW + (size_t)(5*2+p)*NW;
        }
        g.bias = bias6[5];
        g.C = (float*)d_out;
        go.g[0] = g;
        go.g[1] = g; go.g[2] = g; go.g[3] = g; go.g[4] = g;
    }
    gemm_mma_kernel<<<dim3(8, 16, 1), 256, GEMM_SMEM>>>(go);
}

// round 12
// speedup vs baseline: 1.4789x; 1.4789x over previous
#include <cuda_runtime.h>
#include <cuda_bf16.h>
#include <math.h>
#include <stdint.h>

#define SEQ   2048
#define BATCH 2
#define DIM   1024
#define HEADS 16
#define DKH   64
#define NROW  (SEQ*BATCH)   // 4096
#define BH    (BATCH*HEADS) // 32

typedef unsigned long long u64;

// ---------------- mma.sync helpers (portable sm_80+ ISA) ----------------
__device__ __forceinline__ uint32_t smem_to_u32(const void* p) {
    uint32_t a;
    asm("{ .reg .u64 t; cvta.to.shared.u64 t, %1; cvt.u32.u64 %0, t; }" : "=r"(a) : "l"(p));
    return a;
}
__device__ __forceinline__ void cpasync16(uint32_t s, const void* g) {
    asm volatile("cp.async.cg.shared.global [%0], [%1], 16;" :: "r"(s), "l"(g) : "memory");
}
__device__ __forceinline__ void ldsm4(uint32_t* r, uint32_t addr) {
    asm volatile("ldmatrix.sync.aligned.m8n8.x4.shared.b16 {%0,%1,%2,%3}, [%4];"
        : "=r"(r[0]), "=r"(r[1]), "=r"(r[2]), "=r"(r[3]) : "r"(addr));
}
__device__ __forceinline__ void mma16816(float* d, const uint32_t* a, const uint32_t* b) {
    asm volatile("mma.sync.aligned.m16n8k16.row.col.f32.bf16.bf16.f32 "
        "{%0,%1,%2,%3}, {%4,%5,%6,%7}, {%8,%9}, {%0,%1,%2,%3};"
        : "+f"(d[0]), "+f"(d[1]), "+f"(d[2]), "+f"(d[3])
        : "r"(a[0]), "r"(a[1]), "r"(a[2]), "r"(a[3]), "r"(b[0]), "r"(b[1]));
}
// pack (lo=a, hi=b) into bf16x2
__device__ __forceinline__ uint32_t pack2(float lo, float hi) {
    uint32_t r; asm("cvt.rn.bf16x2.f32 %0, %1, %2;" : "=r"(r) : "f"(hi), "f"(lo)); return r;
}

#define SWZ(row, c16) ((row)*128 + ((((c16) ^ ((row)&7)))<<4))

// ---------------- scratch (device globals; no allocation allowed) ----------------
__device__ float g_qx[NROW*DIM];
__device__ float g_kx[NROW*DIM];
__device__ float g_vx[NROW*DIM];
__device__ float g_qc[NROW*DIM];
__device__ float g_kc[NROW*DIM];
__device__ float g_ctx[NROW*DIM];
__device__ __nv_bfloat16 g_sA[5*2*NROW*DIM];
__device__ __nv_bfloat16 g_sW[6*2*DIM*DIM];
__device__ __nv_bfloat16 g_sC[2*NROW*DIM];
__device__ __nv_bfloat16 g_qh[BH*SEQ*DKH];
__device__ __nv_bfloat16 g_ql[BH*SEQ*DKH];
__device__ __nv_bfloat16 g_kh[BH*SEQ*DKH];
__device__ __nv_bfloat16 g_kl[BH*SEQ*DKH];
__device__ __nv_bfloat16 g_vth[BH*DKH*SEQ];
__device__ __nv_bfloat16 g_vtl[BH*DKH*SEQ];

// ================= split2: fp32 -> bf16 hi/lo planes =================
__global__ __launch_bounds__(256)
void split2_kernel(const float4* __restrict__ in, __nv_bfloat16* __restrict__ o1,
                   __nv_bfloat16* __restrict__ o2, int n4) {
    int i = blockIdx.x * blockDim.x + threadIdx.x;
    if (i >= n4) return;
    float4 v = in[i];
    float vv[4] = {v.x, v.y, v.z, v.w};
    union { __nv_bfloat16 h[4]; uint2 u; } p1, p2;
#pragma unroll
    for (int k = 0; k < 4; k++) {
        __nv_bfloat16 a1 = __float2bfloat16(vv[k]);
        float r  = vv[k] - __bfloat162float(a1);
        p1.h[k] = a1; p2.h[k] = __float2bfloat16(r);
    }
    *(uint2*)(o1 + 4*(size_t)i) = p1.u;
    *(uint2*)(o2 + 4*(size_t)i) = p2.u;
}

// ================= weight transpose + split =================
struct WArg  { const float* W; __nv_bfloat16 *o1, *o2; };
struct WArgs { WArg w[6]; };
__global__ __launch_bounds__(256)
void wsplit_kernel(WArgs a) {
    __shared__ float tile[32][33];
    WArg wa = a.w[blockIdx.z];
    int tx = threadIdx.x, ty = threadIdx.y;
    int x = blockIdx.x * 32 + tx;
    int yb = blockIdx.y * 32;
#pragma unroll
    for (int j = 0; j < 32; j += 8)
        tile[ty + j][tx] = wa.W[(size_t)(yb + ty + j) * DIM + x];
    __syncthreads();
    int xo = blockIdx.y * 32 + tx;
    int yo = blockIdx.x * 32;
#pragma unroll
    for (int j = 0; j < 32; j += 8) {
        float v = tile[tx][ty + j];
        size_t o = (size_t)(yo + ty + j) * DIM + xo;
        __nv_bfloat16 b1 = __float2bfloat16(v);
        float r  = v - __bfloat162float(b1);
        wa.o1[o] = b1; wa.o2[o] = __float2bfloat16(r);
    }
}

// ================= HMMA bf16x2 GEMM v4: 256x128 CTA, 512 thr, warp tile 32x64 =================
// Per stage: A1|A2 (32KB each, 256 rows x 128B) and B1|B2 (16KB each).
// 2-stage double buffer; 16 warps (8 m-groups x 2 n-groups) -> 4 warps/SMSP.
#define GBK 64
#define A_TILE_B 32768
#define B_TILE_B 16384
#define GSTAGE_B (2*A_TILE_B + 2*B_TILE_B)   // 98304
#define GEMM_SMEM (2*GSTAGE_B)               // 196608
#define GNCH 16

struct GArg  { const __nv_bfloat16* A[2]; const __nv_bfloat16* B[2]; const float* bias; float* C; };
struct GArgs { GArg g[5]; };

__global__ __launch_bounds__(512, 1)
void gemm_mma_kernel(GArgs args) {
    extern __shared__ char smem[];
    const uint32_t sb = smem_to_u32(smem);
    GArg ga = args.g[blockIdx.z];
    const int t = threadIdx.x;
    const int wid = t >> 5, lane = t & 31;
    const int wm = wid & 7, wn = wid >> 3;      // 8 x 2 warps, warp tile 32x64
    const int m0 = blockIdx.y * 256, n0 = blockIdx.x * 128;

    float acc[2][8][4];
#pragma unroll
    for (int i = 0; i < 2; i++)
#pragma unroll
        for (int j = 0; j < 8; j++)
#pragma unroll
            for (int k = 0; k < 4; k++) acc[i][j][k] = 0.f;

    auto issue = [&](int c) {
        const int kc = c * GBK;
        const uint32_t st = sb + (c & 1) * GSTAGE_B;
        // A planes: 256 rows x 8 c16 each = 2048 lines, 4 iters of 512
#pragma unroll
        for (int p = 0; p < 2; p++) {
            const __nv_bfloat16* base = ga.A[p];
            const uint32_t tb = st + p * A_TILE_B;
#pragma unroll
            for (int i = 0; i < 4; i++) {
                int e = i * 512 + t;
                int c16 = e & 7, row = e >> 3;
                cpasync16(tb + SWZ(row, c16),
                          base + (size_t)(m0 + row) * DIM + kc + c16 * 8);
            }
        }
        // B planes: 128 rows x 8 c16 each = 1024 lines, 2 iters of 512
#pragma unroll
        for (int p = 0; p < 2; p++) {
            const __nv_bfloat16* base = ga.B[p];
            const uint32_t tb = st + 2 * A_TILE_B + p * B_TILE_B;
#pragma unroll
            for (int i = 0; i < 2; i++) {
                int e = i * 512 + t;
                int c16 = e & 7, row = e >> 3;
                cpasync16(tb + SWZ(row, c16),
                          base + (size_t)(n0 + row) * DIM + kc + c16 * 8);
            }
        }
        asm volatile("cp.async.commit_group;" ::: "memory");
    };

    issue(0); issue(1);

    for (int c = 0; c < GNCH; c++) {
        if (c + 1 < GNCH) {
            asm volatile("cp.async.wait_group 1;" ::: "memory");
        } else {
            asm volatile("cp.async.wait_group 0;" ::: "memory");
        }
        __syncthreads();

        const uint32_t st = sb + (c & 1) * GSTAGE_B;
        const uint32_t A1 = st, A2 = st + A_TILE_B;
        const uint32_t B1 = st + 2*A_TILE_B, B2 = B1 + B_TILE_B;
#pragma unroll
        for (int ks = 0; ks < 4; ks++) {
            uint32_t af1[2][4], af2[2][4];
            {
                int ar = wm*32 + (lane & 15);
                int ac16 = ks*2 + ((lane >> 4) & 1);
                ldsm4(af1[0], A1 + SWZ(ar,      ac16));
                ldsm4(af1[1], A1 + SWZ(ar + 16, ac16));
                ldsm4(af2[0], A2 + SWZ(ar,      ac16));
                ldsm4(af2[1], A2 + SWZ(ar + 16, ac16));
            }
            uint32_t bb1[4][4], bb2[4][4];
            {
                int br = (lane & 7) + ((lane >> 4) & 1) * 8;
                int bc16 = ks*2 + ((lane >> 3) & 1);
#pragma unroll
                for (int g = 0; g < 4; g++) {
                    int rr = wn*64 + g*16 + br;
                    ldsm4(bb1[g], B1 + SWZ(rr, bc16));
                    ldsm4(bb2[g], B2 + SWZ(rr, bc16));
                }
            }
#pragma unroll
            for (int tm = 0; tm < 2; tm++)
#pragma unroll
                for (int tn = 0; tn < 8; tn++) {
                    mma16816(acc[tm][tn], af1[tm], &bb1[tn >> 1][(tn & 1) * 2]);
                    mma16816(acc[tm][tn], af2[tm], &bb1[tn >> 1][(tn & 1) * 2]);
                    mma16816(acc[tm][tn], af1[tm], &bb2[tn >> 1][(tn & 1) * 2]);
                }
        }
        __syncthreads();
        if (c + 2 < GNCH) issue(c + 2);
    }

    // epilogue: fragment layout -> C + bias (float2 stores)
#pragma unroll
    for (int tm = 0; tm < 2; tm++) {
        int r0 = m0 + wm*32 + tm*16 + lane / 4;
#pragma unroll
        for (int tn = 0; tn < 8; tn++) {
            int cc = n0 + wn*64 + tn*8 + (lane % 4) * 2;
            float2 bv = *(const float2*)&ga.bias[cc];
            float2 v0 = make_float2(acc[tm][tn][0] + bv.x, acc[tm][tn][1] + bv.y);
            float2 v1 = make_float2(acc[tm][tn][2] + bv.x, acc[tm][tn][3] + bv.y);
            *(float2*)&ga.C[(size_t)r0 * DIM + cc] = v0;
            *(float2*)&ga.C[(size_t)(r0 + 8) * DIM + cc] = v1;
        }
    }
}

// ---------------- lambda gate + mix -> bf16 planes [bh][s][dk] ----------------
__global__ __launch_bounds__(256)
void lam_mix_kernel(const float* __restrict__ Wvqx, const float* __restrict__ bvqx,
                    const float* __restrict__ Wvqc, const float* __restrict__ bvqc,
                    const float* __restrict__ Wvkx, const float* __restrict__ bvkx,
                    const float* __restrict__ Wvkc, const float* __restrict__ bvkc) {
    const int r   = blockIdx.x;
    const bool isK = (blockIdx.y != 0);
    const float* a = isK ? g_kx : g_qx;
    const float* c = isK ? g_kc : g_qc;
    const float* Wa = isK ? Wvkx : Wvqx;
    const float* Wc = isK ? Wvkc : Wvqc;
    const float bsum = isK ? (bvkx[0] + bvkc[0]) : (bvqx[0] + bvqc[0]);
    __nv_bfloat16* oh = isK ? g_kh : g_qh;
    __nv_bfloat16* ol = isK ? g_kl : g_ql;

    const int t = threadIdx.x;
    const int s = r >> 1, b = r & 1;
    float av[4], cv[4];
    float part = 0.f;
#pragma unroll
    for (int i = 0; i < 4; i++) {
        int d = t + i*256;
        av[i] = a[(size_t)r*1024 + d];
        cv[i] = c[(size_t)r*1024 + d];
        part += av[i]*Wa[d] + cv[i]*Wc[d];
    }
    __shared__ float red[256];
    red[t] = part;
    __syncthreads();
    for (int ss = 128; ss > 0; ss >>= 1) {
        if (t < ss) red[t] += red[t+ss];
        __syncthreads();
    }
    float lam = 1.f / (1.f + __expf(-(red[0] + bsum)));
#pragma unroll
    for (int i = 0; i < 4; i++) {
        int d = t + i*256;
        float m = av[i] + lam*(cv[i] - av[i]);
        int hh = d >> 6, dk = d & 63;
        size_t off = ((size_t)(b*HEADS + hh)*SEQ + s)*DKH + dk;
        __nv_bfloat16 mh = __float2bfloat16(m);
        oh[off] = mh;
        ol[off] = __float2bfloat16(m - __bfloat162float(mh));
    }
}

// ---------------- V transpose + split: g_vx -> Vt planes [bh][dk][s] ----------------
__global__ __launch_bounds__(256)
void vsplit_kernel() {
    __shared__ float tile[64][65];
    const int t = threadIdx.x;
    const int s0 = blockIdx.x * 64, bh = blockIdx.y;
    const int b = bh >> 4, h = bh & 15;
#pragma unroll
    for (int i = 0; i < 4; i++) {
        int e = i*256 + t;
        int sr = e >> 4, c4 = e & 15;
        float4 v = *(const float4*)&g_vx[((size_t)(s0+sr)*BATCH + b)*DIM + h*DKH + c4*4];
        tile[sr][c4*4+0] = v.x; tile[sr][c4*4+1] = v.y;
        tile[sr][c4*4+2] = v.z; tile[sr][c4*4+3] = v.w;
    }
    __syncthreads();
    const int dkr = t >> 2, sc = (t & 3) * 16;
    union { __nv_bfloat16 h[8]; uint4 u; } hp[2], lp[2];
#pragma unroll
    for (int ch = 0; ch < 2; ch++)
#pragma unroll
        for (int k = 0; k < 8; k++) {
            float v = tile[sc + ch*8 + k][dkr];
            __nv_bfloat16 hb = __float2bfloat16(v);
            hp[ch].h[k] = hb;
            lp[ch].h[k] = __float2bfloat16(v - __bfloat162float(hb));
        }
    size_t off = ((size_t)bh*DKH + dkr)*SEQ + s0 + sc;
    *(uint4*)&g_vth[off] = hp[0].u; *(uint4*)&g_vth[off+8] = hp[1].u;
    *(uint4*)&g_vtl[off] = lp[0].u; *(uint4*)&g_vtl[off+8] = lp[1].u;
}

// ---------------- HMMA flash attention ----------------
#define FL_SMEM (32768 + 2*32768)

__global__ __launch_bounds__(256)
void flash_mma_kernel() {
    extern __shared__ char fsm[];
    const uint32_t sb = smem_to_u32(fsm);
    const int t = threadIdx.x, lane = t & 31, w = t >> 5;
    const int q0 = blockIdx.x * 128, bh = blockIdx.y;
    const int row0 = w * 16;

    {
        size_t qoff = ((size_t)bh*SEQ + q0)*DKH;
#pragma unroll
        for (int i = 0; i < 8; i++) {
            int e = i*256 + t;
            int c16 = e & 7, row = (e >> 3) & 127, pl = e >> 10;
            const __nv_bfloat16* src = (pl ? g_ql : g_qh) + qoff + row*DKH + c16*8;
            cpasync16(sb + pl*16384 + SWZ(row, c16), src);
        }
        asm volatile("cp.async.commit_group;" ::: "memory");
    }
    auto issue_kv = [&](int kt, int st) {
        int k0 = kt * 64;
#pragma unroll
        for (int i = 0; i < 8; i++) {
            int e = i*256 + t;
            int c16 = e & 7, row = (e >> 3) & 63, pl = e >> 9;
            const __nv_bfloat16* src;
            if (pl < 2) src = (pl ? g_kl : g_kh) + ((size_t)bh*SEQ + k0 + row)*DKH + c16*8;
            else src = (pl == 3 ? g_vtl : g_vth) + ((size_t)bh*DKH + row)*SEQ + k0 + c16*8;
            cpasync16(sb + 32768 + st*32768 + pl*8192 + SWZ(row, c16), src);
        }
        asm volatile("cp.async.commit_group;" ::: "memory");
    };
    issue_kv(0, 0);

    float m0r = -1e30f, m1r = -1e30f, l0 = 0.f, l1 = 0.f;
    float oacc[8][4];
#pragma unroll
    for (int j = 0; j < 8; j++)
#pragma unroll
        for (int k = 0; k < 4; k++) oacc[j][k] = 0.f;

    for (int kt = 0; kt < 32; kt++) {
        const int st = kt & 1;
        if (kt + 1 < 32) {
            issue_kv(kt + 1, st ^ 1);
            asm volatile("cp.async.wait_group 1;" ::: "memory");
        } else {
            asm volatile("cp.async.wait_group 0;" ::: "memory");
        }
        __syncthreads();

        const uint32_t Kh = sb + 32768 + st*32768;
        const uint32_t Kl = Kh + 8192, Vh = Kh + 16384, Vl = Kh + 24576;

        float sacc[8][4];
#pragma unroll
        for (int j = 0; j < 8; j++)
#pragma unroll
            for (int k = 0; k < 4; k++) sacc[j][k] = 0.f;

#pragma unroll
        for (int ks = 0; ks < 4; ks++) {
            uint32_t a1[4], a2[4];
            {
                int r = row0 + (lane & 15);
                int c16 = ks*2 + ((lane >> 4) & 1);
                ldsm4(a1, sb + SWZ(r, c16));
                ldsm4(a2, sb + 16384 + SWZ(r, c16));
            }
            uint32_t bb[4][4];
            int br = (lane & 7) + ((lane >> 4) & 1) * 8;
            int bc16 = ks*2 + ((lane >> 3) & 1);
#pragma unroll
            for (int g = 0; g < 4; g++) { int rr = g*16 + br; ldsm4(bb[g], Kh + SWZ(rr, bc16)); }
#pragma unroll
            for (int j = 0; j < 8; j++) mma16816(sacc[j], a1, &bb[j>>1][(j&1)*2]);
#pragma unroll
            for (int j = 0; j < 8; j++) mma16816(sacc[j], a2, &bb[j>>1][(j&1)*2]);
#pragma unroll
            for (int g = 0; g < 4; g++) { int rr = g*16 + br; ldsm4(bb[g], Kl + SWZ(rr, bc16)); }
#pragma unroll
            for (int j = 0; j < 8; j++) mma16816(sacc[j], a1, &bb[j>>1][(j&1)*2]);
        }

        float mx0 = -1e30f, mx1 = -1e30f;
#pragma unroll
        for (int j = 0; j < 8; j++) {
#pragma unroll
            for (int k = 0; k < 4; k++) sacc[j][k] *= 0.125f;
            mx0 = fmaxf(mx0, fmaxf(sacc[j][0], sacc[j][1]));
            mx1 = fmaxf(mx1, fmaxf(sacc[j][2], sacc[j][3]));
        }
        mx0 = fmaxf(mx0, __shfl_xor_sync(0xffffffffu, mx0, 1));
        mx0 = fmaxf(mx0, __shfl_xor_sync(0xffffffffu, mx0, 2));
        mx1 = fmaxf(mx1, __shfl_xor_sync(0xffffffffu, mx1, 1));
        mx1 = fmaxf(mx1, __shfl_xor_sync(0xffffffffu, mx1, 2));
        float mn0 = fmaxf(m0r, mx0), mn1 = fmaxf(m1r, mx1);
        float corr0 = __expf(m0r - mn0), corr1 = __expf(m1r - mn1);
        m0r = mn0; m1r = mn1;
        float rs0 = 0.f, rs1 = 0.f;
#pragma unroll
        for (int j = 0; j < 8; j++) {
            sacc[j][0] = __expf(sacc[j][0] - mn0);
            sacc[j][1] = __expf(sacc[j][1] - mn0);
            sacc[j][2] = __expf(sacc[j][2] - mn1);
            sacc[j][3] = __expf(sacc[j][3] - mn1);
            rs0 += sacc[j][0] + sacc[j][1];
            rs1 += sacc[j][2] + sacc[j][3];
            oacc[j][0] *= corr0; oacc[j][1] *= corr0;
            oacc[j][2] *= corr1; oacc[j][3] *= corr1;
        }
        rs0 += __shfl_xor_sync(0xffffffffu, rs0, 1);
        rs0 += __shfl_xor_sync(0xffffffffu, rs0, 2);
        rs1 += __shfl_xor_sync(0xffffffffu, rs1, 1);
        rs1 += __shfl_xor_sync(0xffffffffu, rs1, 2);
        l0 = l0*corr0 + rs0;
        l1 = l1*corr1 + rs1;

        uint32_t ph[4][4], pl[4][4];
#pragma unroll
        for (int ks = 0; ks < 4; ks++) {
            int j0 = 2*ks, j1 = 2*ks + 1;
            float p00 = sacc[j0][0], p01 = sacc[j0][1], p02 = sacc[j0][2], p03 = sacc[j0][3];
            float p10 = sacc[j1][0], p11 = sacc[j1][1], p12 = sacc[j1][2], p13 = sacc[j1][3];
            uint32_t h0 = pack2(p00, p01), h1 = pack2(p02, p03);
            uint32_t h2 = pack2(p10, p11), h3 = pack2(p12, p13);
            ph[ks][0] = h0; ph[ks][1] = h1; ph[ks][2] = h2; ph[ks][3] = h3;
            pl[ks][0] = pack2(p00 - __uint_as_float(h0 << 16), p01 - __uint_as_float(h0 & 0xffff0000u));
            pl[ks][1] = pack2(p02 - __uint_as_float(h1 << 16), p03 - __uint_as_float(h1 & 0xffff0000u));
            pl[ks][2] = pack2(p10 - __uint_as_float(h2 << 16), p11 - __uint_as_float(h2 & 0xffff0000u));
            pl[ks][3] = pack2(p12 - __uint_as_float(h3 << 16), p13 - __uint_as_float(h3 & 0xffff0000u));
        }

#pragma unroll
        for (int ks = 0; ks < 4; ks++) {
            uint32_t bb[4][4];
            int br = (lane & 7) + ((lane >> 4) & 1) * 8;
            int bc16 = ks*2 + ((lane >> 3) & 1);
#pragma unroll
            for (int g = 0; g < 4; g++) { int rr = g*16 + br; ldsm4(bb[g], Vh + SWZ(rr, bc16)); }
#pragma unroll
            for (int j = 0; j < 8; j++) mma16816(oacc[j], ph[ks], &bb[j>>1][(j&1)*2]);
#pragma unroll
            for (int j = 0; j < 8; j++) mma16816(oacc[j], pl[ks], &bb[j>>1][(j&1)*2]);
#pragma unroll
            for (int g = 0; g < 4; g++) { int rr = g*16 + br; ldsm4(bb[g], Vl + SWZ(rr, bc16)); }
#pragma unroll
            for (int j = 0; j < 8; j++) mma16816(oacc[j], ph[ks], &bb[j>>1][(j&1)*2]);
        }
        __syncthreads();
    }

    const float inv0 = 1.f / l0, inv1 = 1.f / l1;
    const int b = bh >> 4, h = bh & 15;
    const int sg = q0 + row0 + (lane >> 2);
#pragma unroll
    for (int j = 0; j < 8; j++) {
        int dk = j*8 + (lane & 3)*2;
        float2 v0 = make_float2(oacc[j][0]*inv0, oacc[j][1]*inv0);
        float2 v1 = make_float2(oacc[j][2]*inv1, oacc[j][3]*inv1);
        *(float2*)&g_ctx[((size_t)sg*BATCH + b)*DIM + h*DKH + dk] = v0;
        *(float2*)&g_ctx[((size_t)(sg+8)*BATCH + b)*DIM + h*DKH + dk] = v1;
    }
}

// ---------------- launch ----------------
extern "C" void kernel_launch(void* const* d_in, const int* in_sizes, int n_in,
                              void* d_out, int out_size) {
    const float* in5[5]  = {(const float*)d_in[0], (const float*)d_in[1], (const float*)d_in[2],
                            (const float*)d_in[3], (const float*)d_in[4]};
    const float* W6[6]   = {(const float*)d_in[5],  (const float*)d_in[7],  (const float*)d_in[9],
                            (const float*)d_in[11], (const float*)d_in[13], (const float*)d_in[15]};
    const float* bias6[6]= {(const float*)d_in[6],  (const float*)d_in[8],  (const float*)d_in[10],
                            (const float*)d_in[12], (const float*)d_in[14], (const float*)d_in[16]};
    const float* W_Vqx= (const float*)d_in[17];
    const float* b_Vqx= (const float*)d_in[18];
    const float* W_Vqc= (const float*)d_in[19];
    const float* b_Vqc= (const float*)d_in[20];
    const float* W_Vkx= (const float*)d_in[21];
    const float* b_Vkx= (const float*)d_in[22];
    const float* W_Vkc= (const float*)d_in[23];
    const float* b_Vkc= (const float*)d_in[24];

    float *p_out5[5], *p_ctx;
    cudaGetSymbolAddress((void**)&p_out5[0], g_qx);
    cudaGetSymbolAddress((void**)&p_out5[1], g_kx);
    cudaGetSymbolAddress((void**)&p_out5[2], g_vx);
    cudaGetSymbolAddress((void**)&p_out5[3], g_qc);
    cudaGetSymbolAddress((void**)&p_out5[4], g_kc);
    cudaGetSymbolAddress((void**)&p_ctx,     g_ctx);
    __nv_bfloat16 *pA, *pW, *pC;
    cudaGetSymbolAddress((void**)&pA, g_sA);
    cudaGetSymbolAddress((void**)&pW, g_sW);
    cudaGetSymbolAddress((void**)&pC, g_sC);

    const size_t NA = (size_t)NROW * DIM;
    const size_t NW = (size_t)DIM * DIM;
    const int n4 = (int)(NA / 4);

    // 1) split inputs into bf16 hi/lo planes
    for (int i = 0; i < 5; i++)
        split2_kernel<<<n4/256, 256>>>((const float4*)in5[i],
                                       pA + (size_t)(i*2+0)*NA,
                                       pA + (size_t)(i*2+1)*NA, n4);

    // 2) transpose + split weights
    WArgs wa;
    for (int i = 0; i < 6; i++)
        wa.w[i] = { W6[i], pW + (size_t)(i*2+0)*NW, pW + (size_t)(i*2+1)*NW };
    wsplit_kernel<<<dim3(32, 32, 6), dim3(32, 8)>>>(wa);

    // 3) five projections on HMMA tensor cores (256x128 tiles, 512 thr)
    cudaFuncSetAttribute(gemm_mma_kernel, cudaFuncAttributeMaxDynamicSharedMemorySize, GEMM_SMEM);
    GArgs ga;
    for (int i = 0; i < 5; i++) {
        GArg g;
        for (int p = 0; p < 2; p++) {
            g.A[p] = pA + (size_t)(i*2+p)*NA;
            g.B[p] = pW + (size_t)(i*2+p)*NW;
        }
        g.bias = bias6[i];
        g.C = p_out5[i];
        ga.g[i] = g;
    }
    gemm_mma_kernel<<<dim3(8, 16, 5), 512, GEMM_SMEM>>>(ga);

    // 4) lambda gates + mixing -> bf16 planes; V transpose+split
    lam_mix_kernel<<<dim3(NROW, 2), 256>>>(W_Vqx, b_Vqx, W_Vqc, b_Vqc,
                                           W_Vkx, b_Vkx, W_Vkc, b_Vkc);
    vsplit_kernel<<<dim3(SEQ/64, BH), 256>>>();

    // 5) HMMA flash attention
    cudaFuncSetAttribute(flash_mma_kernel, cudaFuncAttributeMaxDynamicSharedMemorySize, FL_SMEM);
    flash_mma_kernel<<<dim3(SEQ/128, BH), 256, FL_SMEM>>>();

    // 6) split ctx, then output projection into d_out
    split2_kernel<<<n4/256, 256>>>((const float4*)p_ctx, pC, pC + NA, n4);
    GArgs go;
    {
        GArg g;
        for (int p = 0; p < 2; p++) {
            g.A[p] = pC + (size_t)p*NA;
            g.B[p] = pW + (size_t)(5*2+p)*NW;
        }
        g.bias = bias6[5];
        g.C = (float*)d_out;
        go.g[0] = g;
        go.g[1] = g; go.g[2] = g; go.g[3] = g; go.g[4] = g;
    }
    gemm_mma_kernel<<<dim3(8, 16, 1), 512, GEMM_SMEM>>>(go);
}

// round 13
// speedup vs baseline: 1.9448x; 1.3151x over previous
#include <cuda_runtime.h>
#include <cuda_bf16.h>
#include <cuda_fp16.h>
#include <math.h>
#include <stdint.h>

#define SEQ   2048
#define BATCH 2
#define DIM   1024
#define HEADS 16
#define DKH   64
#define NROW  (SEQ*BATCH)   // 4096
#define BH    (BATCH*HEADS) // 32

// ---------------- mma.sync helpers (portable sm_80+ ISA) ----------------
__device__ __forceinline__ uint32_t smem_to_u32(const void* p) {
    uint32_t a;
    asm("{ .reg .u64 t; cvta.to.shared.u64 t, %1; cvt.u32.u64 %0, t; }" : "=r"(a) : "l"(p));
    return a;
}
__device__ __forceinline__ void cpasync16(uint32_t s, const void* g) {
    asm volatile("cp.async.cg.shared.global [%0], [%1], 16;" :: "r"(s), "l"(g) : "memory");
}
__device__ __forceinline__ void ldsm4(uint32_t* r, uint32_t addr) {
    asm volatile("ldmatrix.sync.aligned.m8n8.x4.shared.b16 {%0,%1,%2,%3}, [%4];"
        : "=r"(r[0]), "=r"(r[1]), "=r"(r[2]), "=r"(r[3]) : "r"(addr));
}
__device__ __forceinline__ void mma16816bf(float* d, const uint32_t* a, const uint32_t* b) {
    asm volatile("mma.sync.aligned.m16n8k16.row.col.f32.bf16.bf16.f32 "
        "{%0,%1,%2,%3}, {%4,%5,%6,%7}, {%8,%9}, {%0,%1,%2,%3};"
        : "+f"(d[0]), "+f"(d[1]), "+f"(d[2]), "+f"(d[3])
        : "r"(a[0]), "r"(a[1]), "r"(a[2]), "r"(a[3]), "r"(b[0]), "r"(b[1]));
}
__device__ __forceinline__ void mma16816h(float* d, const uint32_t* a, const uint32_t* b) {
    asm volatile("mma.sync.aligned.m16n8k16.row.col.f32.f16.f16.f32 "
        "{%0,%1,%2,%3}, {%4,%5,%6,%7}, {%8,%9}, {%0,%1,%2,%3};"
        : "+f"(d[0]), "+f"(d[1]), "+f"(d[2]), "+f"(d[3])
        : "r"(a[0]), "r"(a[1]), "r"(a[2]), "r"(a[3]), "r"(b[0]), "r"(b[1]));
}
// pack (lo=a, hi=b) into bf16x2
__device__ __forceinline__ uint32_t pack2(float lo, float hi) {
    uint32_t r; asm("cvt.rn.bf16x2.f32 %0, %1, %2;" : "=r"(r) : "f"(hi), "f"(lo)); return r;
}
// pack (lo, hi) into f16x2
__device__ __forceinline__ uint32_t pack2h(float lo, float hi) {
    uint32_t r; asm("cvt.rn.f16x2.f32 %0, %1, %2;" : "=r"(r) : "f"(hi), "f"(lo)); return r;
}

#define SWZ(row, c16) ((row)*128 + ((((c16) ^ ((row)&7)))<<4))

// ---------------- scratch (device globals; no allocation allowed) ----------------
__device__ float g_qx[NROW*DIM];
__device__ float g_kx[NROW*DIM];
__device__ float g_vx[NROW*DIM];
__device__ float g_qc[NROW*DIM];
__device__ float g_kc[NROW*DIM];
__device__ __half g_hA[5*NROW*DIM];     // 5 inputs, fp16
__device__ __half g_hW[6*DIM*DIM];      // 6 weights (transposed), fp16
__device__ __half g_ctxh[NROW*DIM];     // attention output, fp16
__device__ __nv_bfloat16 g_qh[BH*SEQ*DKH];
__device__ __nv_bfloat16 g_ql[BH*SEQ*DKH];
__device__ __nv_bfloat16 g_kh[BH*SEQ*DKH];
__device__ __nv_bfloat16 g_kl[BH*SEQ*DKH];
__device__ __nv_bfloat16 g_vth[BH*DKH*SEQ];
__device__ __nv_bfloat16 g_vtl[BH*DKH*SEQ];

// ================= tofp16: batched fp32 -> fp16 for the 5 inputs =================
struct CvtArgs { const float4* in[5]; __half* out[5]; };
__global__ __launch_bounds__(256)
void tofp16_kernel(CvtArgs a, int n4) {
    int i = blockIdx.x * blockDim.x + threadIdx.x;
    if (i >= n4) return;
    const float4* in = a.in[blockIdx.y];
    __half* out = a.out[blockIdx.y];
    float4 v = in[i];
    union { __half h[4]; uint2 u; } p;
    p.h[0] = __float2half_rn(v.x); p.h[1] = __float2half_rn(v.y);
    p.h[2] = __float2half_rn(v.z); p.h[3] = __float2half_rn(v.w);
    *(uint2*)(out + 4*(size_t)i) = p.u;
}

// ================= weight transpose -> fp16: W[K,N] -> WT[N,K] =================
struct WArg  { const float* W; __half* o; };
struct WArgs { WArg w[6]; };
__global__ __launch_bounds__(256)
void wsplit_kernel(WArgs a) {
    __shared__ float tile[32][33];
    WArg wa = a.w[blockIdx.z];
    int tx = threadIdx.x, ty = threadIdx.y;
    int x = blockIdx.x * 32 + tx;
    int yb = blockIdx.y * 32;
#pragma unroll
    for (int j = 0; j < 32; j += 8)
        tile[ty + j][tx] = wa.W[(size_t)(yb + ty + j) * DIM + x];
    __syncthreads();
    int xo = blockIdx.y * 32 + tx;
    int yo = blockIdx.x * 32;
#pragma unroll
    for (int j = 0; j < 32; j += 8)
        wa.o[(size_t)(yo + ty + j) * DIM + xo] = __float2half_rn(tile[tx][ty + j]);
}

// ================= fp16 HMMA GEMM: C[4096,1024] = A @ W^T + bias =================
// 128x128 tile, BK=64, single term; 4-stage cp.async pipeline (32KB/stage).
#define GBK 64
#define TILE_B 16384
#define GSTAGE_B (2*TILE_B)          // A + B = 32768
#define GSTAGES 4
#define GEMM_SMEM (GSTAGES*GSTAGE_B) // 131072
#define GNCH 16

struct GArg  { const __half* A; const __half* B; const float* bias; float* C; };
struct GArgs { GArg g[5]; };

__global__ __launch_bounds__(256, 1)
void gemm_mma_kernel(GArgs args) {
    extern __shared__ char smem[];
    const uint32_t sb = smem_to_u32(smem);
    GArg ga = args.g[blockIdx.z];
    const int t = threadIdx.x;
    const int wid = t >> 5, lane = t & 31;
    const int wm = wid & 3, wn = wid >> 2;      // 4 x 2 warps, warp tile 32x64
    const int m0 = blockIdx.y * 128, n0 = blockIdx.x * 128;

    float acc[2][8][4];
#pragma unroll
    for (int i = 0; i < 2; i++)
#pragma unroll
        for (int j = 0; j < 8; j++)
#pragma unroll
            for (int k = 0; k < 4; k++) acc[i][j][k] = 0.f;

    auto issue = [&](int c) {
        const int kc = c * GBK;
        const uint32_t st = sb + (c & (GSTAGES-1)) * GSTAGE_B;
#pragma unroll
        for (int i = 0; i < 4; i++) {
            int e = i * 256 + t;
            int c16 = e & 7, row = e >> 3;
            cpasync16(st + SWZ(row, c16),
                      ga.A + (size_t)(m0 + row) * DIM + kc + c16 * 8);
        }
#pragma unroll
        for (int i = 0; i < 4; i++) {
            int e = i * 256 + t;
            int c16 = e & 7, row = e >> 3;
            cpasync16(st + TILE_B + SWZ(row, c16),
                      ga.B + (size_t)(n0 + row) * DIM + kc + c16 * 8);
        }
        asm volatile("cp.async.commit_group;" ::: "memory");
    };

    issue(0); issue(1); issue(2);

    for (int c = 0; c < GNCH; c++) {
        if (c + 3 < GNCH) {
            issue(c + 3);
            asm volatile("cp.async.wait_group 3;" ::: "memory");
        } else if (c + 2 < GNCH) {
            asm volatile("cp.async.wait_group 2;" ::: "memory");
        } else if (c + 1 < GNCH) {
            asm volatile("cp.async.wait_group 1;" ::: "memory");
        } else {
            asm volatile("cp.async.wait_group 0;" ::: "memory");
        }
        __syncthreads();

        const uint32_t st = sb + (c & (GSTAGES-1)) * GSTAGE_B;
        const uint32_t At = st, Bt = st + TILE_B;
#pragma unroll
        for (int ks = 0; ks < 4; ks++) {
            uint32_t af[2][4];
            {
                int ar = wm*32 + (lane & 15);
                int ac16 = ks*2 + ((lane >> 4) & 1);
                ldsm4(af[0], At + SWZ(ar,      ac16));
                ldsm4(af[1], At + SWZ(ar + 16, ac16));
            }
            uint32_t bb[4][4];
            {
                int br = (lane & 7) + ((lane >> 4) & 1) * 8;
                int bc16 = ks*2 + ((lane >> 3) & 1);
#pragma unroll
                for (int g = 0; g < 4; g++)
                    ldsm4(bb[g], Bt + SWZ(wn*64 + g*16 + br, bc16));
            }
#pragma unroll
            for (int tm = 0; tm < 2; tm++)
#pragma unroll
                for (int tn = 0; tn < 8; tn++)
                    mma16816h(acc[tm][tn], af[tm], &bb[tn >> 1][(tn & 1) * 2]);
        }
        __syncthreads();
    }

    // epilogue: fragment layout -> C + bias (float2 stores)
#pragma unroll
    for (int tm = 0; tm < 2; tm++) {
        int r0 = m0 + wm*32 + tm*16 + lane / 4;
#pragma unroll
        for (int tn = 0; tn < 8; tn++) {
            int cc = n0 + wn*64 + tn*8 + (lane % 4) * 2;
            float2 bv = *(const float2*)&ga.bias[cc];
            float2 v0 = make_float2(acc[tm][tn][0] + bv.x, acc[tm][tn][1] + bv.y);
            float2 v1 = make_float2(acc[tm][tn][2] + bv.x, acc[tm][tn][3] + bv.y);
            *(float2*)&ga.C[(size_t)r0 * DIM + cc] = v0;
            *(float2*)&ga.C[(size_t)(r0 + 8) * DIM + cc] = v1;
        }
    }
}

// ---------------- lambda gate + mix -> bf16 planes [bh][s][dk] ----------------
__global__ __launch_bounds__(256)
void lam_mix_kernel(const float* __restrict__ Wvqx, const float* __restrict__ bvqx,
                    const float* __restrict__ Wvqc, const float* __restrict__ bvqc,
                    const float* __restrict__ Wvkx, const float* __restrict__ bvkx,
                    const float* __restrict__ Wvkc, const float* __restrict__ bvkc) {
    const int r   = blockIdx.x;
    const bool isK = (blockIdx.y != 0);
    const float* a = isK ? g_kx : g_qx;
    const float* c = isK ? g_kc : g_qc;
    const float* Wa = isK ? Wvkx : Wvqx;
    const float* Wc = isK ? Wvkc : Wvqc;
    const float bsum = isK ? (bvkx[0] + bvkc[0]) : (bvqx[0] + bvqc[0]);
    __nv_bfloat16* oh = isK ? g_kh : g_qh;
    __nv_bfloat16* ol = isK ? g_kl : g_ql;

    const int t = threadIdx.x;
    const int s = r >> 1, b = r & 1;
    float av[4], cv[4];
    float part = 0.f;
#pragma unroll
    for (int i = 0; i < 4; i++) {
        int d = t + i*256;
        av[i] = a[(size_t)r*1024 + d];
        cv[i] = c[(size_t)r*1024 + d];
        part += av[i]*Wa[d] + cv[i]*Wc[d];
    }
    __shared__ float red[256];
    red[t] = part;
    __syncthreads();
    for (int ss = 128; ss > 0; ss >>= 1) {
        if (t < ss) red[t] += red[t+ss];
        __syncthreads();
    }
    float lam = 1.f / (1.f + __expf(-(red[0] + bsum)));
#pragma unroll
    for (int i = 0; i < 4; i++) {
        int d = t + i*256;
        float m = av[i] + lam*(cv[i] - av[i]);
        int hh = d >> 6, dk = d & 63;
        size_t off = ((size_t)(b*HEADS + hh)*SEQ + s)*DKH + dk;
        __nv_bfloat16 mh = __float2bfloat16(m);
        oh[off] = mh;
        ol[off] = __float2bfloat16(m - __bfloat162float(mh));
    }
}

// ---------------- V transpose + split: g_vx -> Vt planes [bh][dk][s] ----------------
__global__ __launch_bounds__(256)
void vsplit_kernel() {
    __shared__ float tile[64][65];
    const int t = threadIdx.x;
    const int s0 = blockIdx.x * 64, bh = blockIdx.y;
    const int b = bh >> 4, h = bh & 15;
#pragma unroll
    for (int i = 0; i < 4; i++) {
        int e = i*256 + t;
        int sr = e >> 4, c4 = e & 15;
        float4 v = *(const float4*)&g_vx[((size_t)(s0+sr)*BATCH + b)*DIM + h*DKH + c4*4];
        tile[sr][c4*4+0] = v.x; tile[sr][c4*4+1] = v.y;
        tile[sr][c4*4+2] = v.z; tile[sr][c4*4+3] = v.w;
    }
    __syncthreads();
    const int dkr = t >> 2, sc = (t & 3) * 16;
    union { __nv_bfloat16 h[8]; uint4 u; } hp[2], lp[2];
#pragma unroll
    for (int ch = 0; ch < 2; ch++)
#pragma unroll
        for (int k = 0; k < 8; k++) {
            float v = tile[sc + ch*8 + k][dkr];
            __nv_bfloat16 hb = __float2bfloat16(v);
            hp[ch].h[k] = hb;
            lp[ch].h[k] = __float2bfloat16(v - __bfloat162float(hb));
        }
    size_t off = ((size_t)bh*DKH + dkr)*SEQ + s0 + sc;
    *(uint4*)&g_vth[off] = hp[0].u; *(uint4*)&g_vth[off+8] = hp[1].u;
    *(uint4*)&g_vtl[off] = lp[0].u; *(uint4*)&g_vtl[off+8] = lp[1].u;
}

// ---------------- HMMA flash attention (bf16 3-term, unchanged math) ----------------
#define FL_SMEM (32768 + 2*32768)

__global__ __launch_bounds__(256)
void flash_mma_kernel() {
    extern __shared__ char fsm[];
    const uint32_t sb = smem_to_u32(fsm);
    const int t = threadIdx.x, lane = t & 31, w = t >> 5;
    const int q0 = blockIdx.x * 128, bh = blockIdx.y;
    const int row0 = w * 16;

    {
        size_t qoff = ((size_t)bh*SEQ + q0)*DKH;
#pragma unroll
        for (int i = 0; i < 8; i++) {
            int e = i*256 + t;
            int c16 = e & 7, row = (e >> 3) & 127, pl = e >> 10;
            const __nv_bfloat16* src = (pl ? g_ql : g_qh) + qoff + row*DKH + c16*8;
            cpasync16(sb + pl*16384 + SWZ(row, c16), src);
        }
        asm volatile("cp.async.commit_group;" ::: "memory");
    }
    auto issue_kv = [&](int kt, int st) {
        int k0 = kt * 64;
#pragma unroll
        for (int i = 0; i < 8; i++) {
            int e = i*256 + t;
            int c16 = e & 7, row = (e >> 3) & 63, pl = e >> 9;
            const __nv_bfloat16* src;
            if (pl < 2) src = (pl ? g_kl : g_kh) + ((size_t)bh*SEQ + k0 + row)*DKH + c16*8;
            else src = (pl == 3 ? g_vtl : g_vth) + ((size_t)bh*DKH + row)*SEQ + k0 + c16*8;
            cpasync16(sb + 32768 + st*32768 + pl*8192 + SWZ(row, c16), src);
        }
        asm volatile("cp.async.commit_group;" ::: "memory");
    };
    issue_kv(0, 0);

    float m0r = -1e30f, m1r = -1e30f, l0 = 0.f, l1 = 0.f;
    float oacc[8][4];
#pragma unroll
    for (int j = 0; j < 8; j++)
#pragma unroll
        for (int k = 0; k < 4; k++) oacc[j][k] = 0.f;

    for (int kt = 0; kt < 32; kt++) {
        const int st = kt & 1;
        if (kt + 1 < 32) {
            issue_kv(kt + 1, st ^ 1);
            asm volatile("cp.async.wait_group 1;" ::: "memory");
        } else {
            asm volatile("cp.async.wait_group 0;" ::: "memory");
        }
        __syncthreads();

        const uint32_t Kh = sb + 32768 + st*32768;
        const uint32_t Kl = Kh + 8192, Vh = Kh + 16384, Vl = Kh + 24576;

        float sacc[8][4];
#pragma unroll
        for (int j = 0; j < 8; j++)
#pragma unroll
            for (int k = 0; k < 4; k++) sacc[j][k] = 0.f;

#pragma unroll
        for (int ks = 0; ks < 4; ks++) {
            uint32_t a1[4], a2[4];
            {
                int r = row0 + (lane & 15);
                int c16 = ks*2 + ((lane >> 4) & 1);
                ldsm4(a1, sb + SWZ(r, c16));
                ldsm4(a2, sb + 16384 + SWZ(r, c16));
            }
            uint32_t bb[4][4];
            int br = (lane & 7) + ((lane >> 4) & 1) * 8;
            int bc16 = ks*2 + ((lane >> 3) & 1);
#pragma unroll
            for (int g = 0; g < 4; g++) { int rr = g*16 + br; ldsm4(bb[g], Kh + SWZ(rr, bc16)); }
#pragma unroll
            for (int j = 0; j < 8; j++) mma16816bf(sacc[j], a1, &bb[j>>1][(j&1)*2]);
#pragma unroll
            for (int j = 0; j < 8; j++) mma16816bf(sacc[j], a2, &bb[j>>1][(j&1)*2]);
#pragma unroll
            for (int g = 0; g < 4; g++) { int rr = g*16 + br; ldsm4(bb[g], Kl + SWZ(rr, bc16)); }
#pragma unroll
            for (int j = 0; j < 8; j++) mma16816bf(sacc[j], a1, &bb[j>>1][(j&1)*2]);
        }

        float mx0 = -1e30f, mx1 = -1e30f;
#pragma unroll
        for (int j = 0; j < 8; j++) {
#pragma unroll
            for (int k = 0; k < 4; k++) sacc[j][k] *= 0.125f;
            mx0 = fmaxf(mx0, fmaxf(sacc[j][0], sacc[j][1]));
            mx1 = fmaxf(mx1, fmaxf(sacc[j][2], sacc[j][3]));
        }
        mx0 = fmaxf(mx0, __shfl_xor_sync(0xffffffffu, mx0, 1));
        mx0 = fmaxf(mx0, __shfl_xor_sync(0xffffffffu, mx0, 2));
        mx1 = fmaxf(mx1, __shfl_xor_sync(0xffffffffu, mx1, 1));
        mx1 = fmaxf(mx1, __shfl_xor_sync(0xffffffffu, mx1, 2));
        float mn0 = fmaxf(m0r, mx0), mn1 = fmaxf(m1r, mx1);
        float corr0 = __expf(m0r - mn0), corr1 = __expf(m1r - mn1);
        m0r = mn0; m1r = mn1;
        float rs0 = 0.f, rs1 = 0.f;
#pragma unroll
        for (int j = 0; j < 8; j++) {
            sacc[j][0] = __expf(sacc[j][0] - mn0);
            sacc[j][1] = __expf(sacc[j][1] - mn0);
            sacc[j][2] = __expf(sacc[j][2] - mn1);
            sacc[j][3] = __expf(sacc[j][3] - mn1);
            rs0 += sacc[j][0] + sacc[j][1];
            rs1 += sacc[j][2] + sacc[j][3];
            oacc[j][0] *= corr0; oacc[j][1] *= corr0;
            oacc[j][2] *= corr1; oacc[j][3] *= corr1;
        }
        rs0 += __shfl_xor_sync(0xffffffffu, rs0, 1);
        rs0 += __shfl_xor_sync(0xffffffffu, rs0, 2);
        rs1 += __shfl_xor_sync(0xffffffffu, rs1, 1);
        rs1 += __shfl_xor_sync(0xffffffffu, rs1, 2);
        l0 = l0*corr0 + rs0;
        l1 = l1*corr1 + rs1;

        uint32_t ph[4][4], pl[4][4];
#pragma unroll
        for (int ks = 0; ks < 4; ks++) {
            int j0 = 2*ks, j1 = 2*ks + 1;
            float p00 = sacc[j0][0], p01 = sacc[j0][1], p02 = sacc[j0][2], p03 = sacc[j0][3];
            float p10 = sacc[j1][0], p11 = sacc[j1][1], p12 = sacc[j1][2], p13 = sacc[j1][3];
            uint32_t h0 = pack2(p00, p01), h1 = pack2(p02, p03);
            uint32_t h2 = pack2(p10, p11), h3 = pack2(p12, p13);
            ph[ks][0] = h0; ph[ks][1] = h1; ph[ks][2] = h2; ph[ks][3] = h3;
            pl[ks][0] = pack2(p00 - __uint_as_float(h0 << 16), p01 - __uint_as_float(h0 & 0xffff0000u));
            pl[ks][1] = pack2(p02 - __uint_as_float(h1 << 16), p03 - __uint_as_float(h1 & 0xffff0000u));
            pl[ks][2] = pack2(p10 - __uint_as_float(h2 << 16), p11 - __uint_as_float(h2 & 0xffff0000u));
            pl[ks][3] = pack2(p12 - __uint_as_float(h3 << 16), p13 - __uint_as_float(h3 & 0xffff0000u));
        }

#pragma unroll
        for (int ks = 0; ks < 4; ks++) {
            uint32_t bb[4][4];
            int br = (lane & 7) + ((lane >> 4) & 1) * 8;
            int bc16 = ks*2 + ((lane >> 3) & 1);
#pragma unroll
            for (int g = 0; g < 4; g++) { int rr = g*16 + br; ldsm4(bb[g], Vh + SWZ(rr, bc16)); }
#pragma unroll
            for (int j = 0; j < 8; j++) mma16816bf(oacc[j], ph[ks], &bb[j>>1][(j&1)*2]);
#pragma unroll
            for (int j = 0; j < 8; j++) mma16816bf(oacc[j], pl[ks], &bb[j>>1][(j&1)*2]);
#pragma unroll
            for (int g = 0; g < 4; g++) { int rr = g*16 + br; ldsm4(bb[g], Vl + SWZ(rr, bc16)); }
#pragma unroll
            for (int j = 0; j < 8; j++) mma16816bf(oacc[j], ph[ks], &bb[j>>1][(j&1)*2]);
        }
        __syncthreads();
    }

    // epilogue: write ctx directly as fp16 [s*B+b][h*64+dk]
    const float inv0 = 1.f / l0, inv1 = 1.f / l1;
    const int b = bh >> 4, h = bh & 15;
    const int sg = q0 + row0 + (lane >> 2);
#pragma unroll
    for (int j = 0; j < 8; j++) {
        int dk = j*8 + (lane & 3)*2;
        uint32_t w0 = pack2h(oacc[j][0]*inv0, oacc[j][1]*inv0);
        uint32_t w1 = pack2h(oacc[j][2]*inv1, oacc[j][3]*inv1);
        *(uint32_t*)&g_ctxh[((size_t)sg*BATCH + b)*DIM + h*DKH + dk] = w0;
        *(uint32_t*)&g_ctxh[((size_t)(sg+8)*BATCH + b)*DIM + h*DKH + dk] = w1;
    }
}

// ---------------- launch ----------------
extern "C" void kernel_launch(void* const* d_in, const int* in_sizes, int n_in,
                              void* d_out, int out_size) {
    const float* in5[5]  = {(const float*)d_in[0], (const float*)d_in[1], (const float*)d_in[2],
                            (const float*)d_in[3], (const float*)d_in[4]};
    const float* W6[6]   = {(const float*)d_in[5],  (const float*)d_in[7],  (const float*)d_in[9],
                            (const float*)d_in[11], (const float*)d_in[13], (const float*)d_in[15]};
    const float* bias6[6]= {(const float*)d_in[6],  (const float*)d_in[8],  (const float*)d_in[10],
                            (const float*)d_in[12], (const float*)d_in[14], (const float*)d_in[16]};
    const float* W_Vqx= (const float*)d_in[17];
    const float* b_Vqx= (const float*)d_in[18];
    const float* W_Vqc= (const float*)d_in[19];
    const float* b_Vqc= (const float*)d_in[20];
    const float* W_Vkx= (const float*)d_in[21];
    const float* b_Vkx= (const float*)d_in[22];
    const float* W_Vkc= (const float*)d_in[23];
    const float* b_Vkc= (const float*)d_in[24];

    float *p_out5[5];
    cudaGetSymbolAddress((void**)&p_out5[0], g_qx);
    cudaGetSymbolAddress((void**)&p_out5[1], g_kx);
    cudaGetSymbolAddress((void**)&p_out5[2], g_vx);
    cudaGetSymbolAddress((void**)&p_out5[3], g_qc);
    cudaGetSymbolAddress((void**)&p_out5[4], g_kc);
    __half *pA, *pW, *pCtx;
    cudaGetSymbolAddress((void**)&pA,   g_hA);
    cudaGetSymbolAddress((void**)&pW,   g_hW);
    cudaGetSymbolAddress((void**)&pCtx, g_ctxh);

    const size_t NA = (size_t)NROW * DIM;
    const size_t NW = (size_t)DIM * DIM;
    const int n4 = (int)(NA / 4);

    // 1) convert 5 inputs to fp16 (one batched launch)
    CvtArgs ca;
    for (int i = 0; i < 5; i++) {
        ca.in[i]  = (const float4*)in5[i];
        ca.out[i] = pA + (size_t)i * NA;
    }
    tofp16_kernel<<<dim3(n4/256, 5), 256>>>(ca, n4);

    // 2) transpose weights to fp16
    WArgs wa;
    for (int i = 0; i < 6; i++)
        wa.w[i] = { W6[i], pW + (size_t)i * NW };
    wsplit_kernel<<<dim3(32, 32, 6), dim3(32, 8)>>>(wa);

    // 3) five projections, fp16 HMMA
    cudaFuncSetAttribute(gemm_mma_kernel, cudaFuncAttributeMaxDynamicSharedMemorySize, GEMM_SMEM);
    GArgs ga;
    for (int i = 0; i < 5; i++)
        ga.g[i] = { pA + (size_t)i*NA, pW + (size_t)i*NW, bias6[i], p_out5[i] };
    gemm_mma_kernel<<<dim3(8, 32, 5), 256, GEMM_SMEM>>>(ga);

    // 4) lambda gates + mixing -> bf16 planes; V transpose+split
    lam_mix_kernel<<<dim3(NROW, 2), 256>>>(W_Vqx, b_Vqx, W_Vqc, b_Vqc,
                                           W_Vkx, b_Vkx, W_Vkc, b_Vkc);
    vsplit_kernel<<<dim3(SEQ/64, BH), 256>>>();

    // 5) HMMA flash attention (6th launch -> profiled by ncu -s 5 -c 1)
    cudaFuncSetAttribute(flash_mma_kernel, cudaFuncAttributeMaxDynamicSharedMemorySize, FL_SMEM);
    flash_mma_kernel<<<dim3(SEQ/128, BH), 256, FL_SMEM>>>();

    // 6) output projection straight from fp16 ctx into d_out
    GArgs go;
    go.g[0] = { pCtx, pW + (size_t)5*NW, bias6[5], (float*)d_out };
    go.g[1] = go.g[0]; go.g[2] = go.g[0]; go.g[3] = go.g[0]; go.g[4] = go.g[0];
    gemm_mma_kernel<<<dim3(8, 32, 1), 256, GEMM_SMEM>>>(go);
}

// round 14
// speedup vs baseline: 2.5334x; 1.3026x over previous
#include <cuda_runtime.h>
#include <cuda_bf16.h>
#include <cuda_fp16.h>
#include <math.h>
#include <stdint.h>

#define SEQ   2048
#define BATCH 2
#define DIM   1024
#define HEADS 16
#define DKH   64
#define NROW  (SEQ*BATCH)   // 4096
#define BH    (BATCH*HEADS) // 32

// ---------------- mma.sync helpers (portable sm_80+ ISA) ----------------
__device__ __forceinline__ uint32_t smem_to_u32(const void* p) {
    uint32_t a;
    asm("{ .reg .u64 t; cvta.to.shared.u64 t, %1; cvt.u32.u64 %0, t; }" : "=r"(a) : "l"(p));
    return a;
}
__device__ __forceinline__ void cpasync16(uint32_t s, const void* g) {
    asm volatile("cp.async.cg.shared.global [%0], [%1], 16;" :: "r"(s), "l"(g) : "memory");
}
__device__ __forceinline__ void ldsm4(uint32_t* r, uint32_t addr) {
    asm volatile("ldmatrix.sync.aligned.m8n8.x4.shared.b16 {%0,%1,%2,%3}, [%4];"
        : "=r"(r[0]), "=r"(r[1]), "=r"(r[2]), "=r"(r[3]) : "r"(addr));
}
__device__ __forceinline__ void mma16816h(float* d, const uint32_t* a, const uint32_t* b) {
    asm volatile("mma.sync.aligned.m16n8k16.row.col.f32.f16.f16.f32 "
        "{%0,%1,%2,%3}, {%4,%5,%6,%7}, {%8,%9}, {%0,%1,%2,%3};"
        : "+f"(d[0]), "+f"(d[1]), "+f"(d[2]), "+f"(d[3])
        : "r"(a[0]), "r"(a[1]), "r"(a[2]), "r"(a[3]), "r"(b[0]), "r"(b[1]));
}
// pack (lo, hi) into f16x2 (lo -> low half)
__device__ __forceinline__ uint32_t pack2h(float lo, float hi) {
    uint32_t r; asm("cvt.rn.f16x2.f32 %0, %1, %2;" : "=r"(r) : "f"(hi), "f"(lo)); return r;
}

#define SWZ(row, c16) ((row)*128 + ((((c16) ^ ((row)&7)))<<4))

// ---------------- scratch (device globals; no allocation allowed) ----------------
__device__ __half g_hA[5*NROW*DIM];     // 5 inputs, fp16
__device__ __half g_hW[6*DIM*DIM];      // 6 weights (transposed), fp16
__device__ __half g_hP[5*NROW*DIM];     // 5 projection outputs, fp16
__device__ __half g_ctxh[NROW*DIM];     // attention output, fp16
__device__ __half g_qm[BH*SEQ*DKH];     // mixed q, [bh][s][dk]
__device__ __half g_km[BH*SEQ*DKH];     // mixed k
__device__ __half g_vt[BH*DKH*SEQ];     // v transposed, [bh][dk][s]

// ================= tofp16: batched fp32 -> fp16 for the 5 inputs =================
struct CvtArgs { const float4* in[5]; __half* out[5]; };
__global__ __launch_bounds__(256)
void tofp16_kernel(CvtArgs a, int n4) {
    int i = blockIdx.x * blockDim.x + threadIdx.x;
    if (i >= n4) return;
    const float4* in = a.in[blockIdx.y];
    __half* out = a.out[blockIdx.y];
    float4 v = in[i];
    union { __half h[4]; uint2 u; } p;
    p.h[0] = __float2half_rn(v.x); p.h[1] = __float2half_rn(v.y);
    p.h[2] = __float2half_rn(v.z); p.h[3] = __float2half_rn(v.w);
    *(uint2*)(out + 4*(size_t)i) = p.u;
}

// ================= weight transpose -> fp16: W[K,N] -> WT[N,K] =================
struct WArg  { const float* W; __half* o; };
struct WArgs { WArg w[6]; };
__global__ __launch_bounds__(256)
void wsplit_kernel(WArgs a) {
    __shared__ float tile[32][33];
    WArg wa = a.w[blockIdx.z];
    int tx = threadIdx.x, ty = threadIdx.y;
    int x = blockIdx.x * 32 + tx;
    int yb = blockIdx.y * 32;
#pragma unroll
    for (int j = 0; j < 32; j += 8)
        tile[ty + j][tx] = wa.W[(size_t)(yb + ty + j) * DIM + x];
    __syncthreads();
    int xo = blockIdx.y * 32 + tx;
    int yo = blockIdx.x * 32;
#pragma unroll
    for (int j = 0; j < 32; j += 8)
        wa.o[(size_t)(yo + ty + j) * DIM + xo] = __float2half_rn(tile[tx][ty + j]);
}

// ================= fp16 HMMA GEMM: C = A @ W^T + bias (fp32 or fp16 out) =================
#define GBK 64
#define TILE_B 16384
#define GSTAGE_B (2*TILE_B)          // 32768
#define GSTAGES 4
#define GEMM_SMEM (GSTAGES*GSTAGE_B) // 131072
#define GNCH 16

struct GArg  { const __half* A; const __half* B; const float* bias; float* C32; __half* C16; };
struct GArgs { GArg g[5]; };

__global__ __launch_bounds__(256, 1)
void gemm_mma_kernel(GArgs args) {
    extern __shared__ char smem[];
    const uint32_t sb = smem_to_u32(smem);
    GArg ga = args.g[blockIdx.z];
    const int t = threadIdx.x;
    const int wid = t >> 5, lane = t & 31;
    const int wm = wid & 3, wn = wid >> 2;
    const int m0 = blockIdx.y * 128, n0 = blockIdx.x * 128;

    float acc[2][8][4];
#pragma unroll
    for (int i = 0; i < 2; i++)
#pragma unroll
        for (int j = 0; j < 8; j++)
#pragma unroll
            for (int k = 0; k < 4; k++) acc[i][j][k] = 0.f;

    auto issue = [&](int c) {
        const int kc = c * GBK;
        const uint32_t st = sb + (c & (GSTAGES-1)) * GSTAGE_B;
#pragma unroll
        for (int i = 0; i < 4; i++) {
            int e = i * 256 + t;
            int c16 = e & 7, row = e >> 3;
            cpasync16(st + SWZ(row, c16),
                      ga.A + (size_t)(m0 + row) * DIM + kc + c16 * 8);
        }
#pragma unroll
        for (int i = 0; i < 4; i++) {
            int e = i * 256 + t;
            int c16 = e & 7, row = e >> 3;
            cpasync16(st + TILE_B + SWZ(row, c16),
                      ga.B + (size_t)(n0 + row) * DIM + kc + c16 * 8);
        }
        asm volatile("cp.async.commit_group;" ::: "memory");
    };

    issue(0); issue(1); issue(2);

    for (int c = 0; c < GNCH; c++) {
        if (c + 3 < GNCH) {
            issue(c + 3);
            asm volatile("cp.async.wait_group 3;" ::: "memory");
        } else if (c + 2 < GNCH) {
            asm volatile("cp.async.wait_group 2;" ::: "memory");
        } else if (c + 1 < GNCH) {
            asm volatile("cp.async.wait_group 1;" ::: "memory");
        } else {
            asm volatile("cp.async.wait_group 0;" ::: "memory");
        }
        __syncthreads();

        const uint32_t At = sb + (c & (GSTAGES-1)) * GSTAGE_B;
        const uint32_t Bt = At + TILE_B;
#pragma unroll
        for (int ks = 0; ks < 4; ks++) {
            uint32_t af[2][4];
            {
                int ar = wm*32 + (lane & 15);
                int ac16 = ks*2 + ((lane >> 4) & 1);
                ldsm4(af[0], At + SWZ(ar,      ac16));
                ldsm4(af[1], At + SWZ(ar + 16, ac16));
            }
            uint32_t bb[4][4];
            {
                int br = (lane & 7) + ((lane >> 4) & 1) * 8;
                int bc16 = ks*2 + ((lane >> 3) & 1);
#pragma unroll
                for (int g = 0; g < 4; g++)
                    ldsm4(bb[g], Bt + SWZ(wn*64 + g*16 + br, bc16));
            }
#pragma unroll
            for (int tm = 0; tm < 2; tm++)
#pragma unroll
                for (int tn = 0; tn < 8; tn++)
                    mma16816h(acc[tm][tn], af[tm], &bb[tn >> 1][(tn & 1) * 2]);
        }
        __syncthreads();
    }

#pragma unroll
    for (int tm = 0; tm < 2; tm++) {
        int r0 = m0 + wm*32 + tm*16 + lane / 4;
#pragma unroll
        for (int tn = 0; tn < 8; tn++) {
            int cc = n0 + wn*64 + tn*8 + (lane % 4) * 2;
            float2 bv = *(const float2*)&ga.bias[cc];
            float a0 = acc[tm][tn][0] + bv.x, a1 = acc[tm][tn][1] + bv.y;
            float a2 = acc[tm][tn][2] + bv.x, a3 = acc[tm][tn][3] + bv.y;
            if (ga.C16) {
                *(uint32_t*)&ga.C16[(size_t)r0 * DIM + cc]       = pack2h(a0, a1);
                *(uint32_t*)&ga.C16[(size_t)(r0 + 8) * DIM + cc] = pack2h(a2, a3);
            } else {
                *(float2*)&ga.C32[(size_t)r0 * DIM + cc]       = make_float2(a0, a1);
                *(float2*)&ga.C32[(size_t)(r0 + 8) * DIM + cc] = make_float2(a2, a3);
            }
        }
    }
}

// ---------------- lambda gate + mix (fp16 in) -> fp16 [bh][s][dk] ----------------
__global__ __launch_bounds__(256)
void lam_mix_kernel(const float* __restrict__ Wvqx, const float* __restrict__ bvqx,
                    const float* __restrict__ Wvqc, const float* __restrict__ bvqc,
                    const float* __restrict__ Wvkx, const float* __restrict__ bvkx,
                    const float* __restrict__ Wvkc, const float* __restrict__ bvkc) {
    const int r   = blockIdx.x;
    const bool isK = (blockIdx.y != 0);
    const __half* a = g_hP + (isK ? 1 : 0) * (size_t)NROW * DIM;
    const __half* c = g_hP + (isK ? 4 : 3) * (size_t)NROW * DIM;
    const float* Wa = isK ? Wvkx : Wvqx;
    const float* Wc = isK ? Wvkc : Wvqc;
    const float bsum = isK ? (bvkx[0] + bvkc[0]) : (bvqx[0] + bvqc[0]);
    __half* om = isK ? g_km : g_qm;

    const int t = threadIdx.x;
    const int s = r >> 1, b = r & 1;
    const int d0 = t * 4;
    float av[4], cv[4];
    {
        union { uint2 u; __half h[4]; } ua, uc;
        ua.u = *(const uint2*)&a[(size_t)r*1024 + d0];
        uc.u = *(const uint2*)&c[(size_t)r*1024 + d0];
#pragma unroll
        for (int i = 0; i < 4; i++) { av[i] = __half2float(ua.h[i]); cv[i] = __half2float(uc.h[i]); }
    }
    float part = 0.f;
#pragma unroll
    for (int i = 0; i < 4; i++)
        part += av[i]*Wa[d0+i] + cv[i]*Wc[d0+i];
    __shared__ float red[256];
    red[t] = part;
    __syncthreads();
    for (int ss = 128; ss > 0; ss >>= 1) {
        if (t < ss) red[t] += red[t+ss];
        __syncthreads();
    }
    float lam = 1.f / (1.f + __expf(-(red[0] + bsum)));
    const int hh = d0 >> 6, dk = d0 & 63;
    union { uint2 u; __half h[4]; } out;
#pragma unroll
    for (int i = 0; i < 4; i++)
        out.h[i] = __float2half_rn(av[i] + lam*(cv[i] - av[i]));
    *(uint2*)&om[((size_t)(b*HEADS + hh)*SEQ + s)*DKH + dk] = out.u;
}

// ---------------- V transpose: g_hP[vx] -> g_vt [bh][dk][s] ----------------
__global__ __launch_bounds__(256)
void vsplit_kernel() {
    __shared__ float tile[64][65];
    const int t = threadIdx.x;
    const int s0 = blockIdx.x * 64, bh = blockIdx.y;
    const int b = bh >> 4, h = bh & 15;
    const __half* v = g_hP + 2 * (size_t)NROW * DIM;
#pragma unroll
    for (int i = 0; i < 4; i++) {
        int e = i*256 + t;
        int sr = e >> 4, c4 = e & 15;
        union { uint2 u; __half h[4]; } uv;
        uv.u = *(const uint2*)&v[((size_t)(s0+sr)*BATCH + b)*DIM + h*DKH + c4*4];
#pragma unroll
        for (int k = 0; k < 4; k++) tile[sr][c4*4+k] = __half2float(uv.h[k]);
    }
    __syncthreads();
    const int dkr = t >> 2, sc = (t & 3) * 16;
    union { __half h[8]; uint4 u; } hp[2];
#pragma unroll
    for (int ch = 0; ch < 2; ch++)
#pragma unroll
        for (int k = 0; k < 8; k++)
            hp[ch].h[k] = __float2half_rn(tile[sc + ch*8 + k][dkr]);
    size_t off = ((size_t)bh*DKH + dkr)*SEQ + s0 + sc;
    *(uint4*)&g_vt[off] = hp[0].u; *(uint4*)&g_vt[off+8] = hp[1].u;
}

// ---------------- fp16 HMMA flash attention ----------------
// Q 16KB | 2 stages x {K 8KB | V 8KB}; QK 1 term, PV 2 terms (P hi + residual).
#define FL_SMEM (16384 + 2*16384)

__global__ __launch_bounds__(256)
void flash_mma_kernel() {
    extern __shared__ char fsm[];
    const uint32_t sb = smem_to_u32(fsm);
    const int t = threadIdx.x, lane = t & 31, w = t >> 5;
    const int q0 = blockIdx.x * 128, bh = blockIdx.y;
    const int row0 = w * 16;

    {
        size_t qoff = ((size_t)bh*SEQ + q0)*DKH;
#pragma unroll
        for (int i = 0; i < 4; i++) {
            int e = i*256 + t;
            int c16 = e & 7, row = e >> 3;
            cpasync16(sb + SWZ(row, c16), g_qm + qoff + row*DKH + c16*8);
        }
        asm volatile("cp.async.commit_group;" ::: "memory");
    }
    auto issue_kv = [&](int kt, int st) {
        int k0 = kt * 64;
#pragma unroll
        for (int i = 0; i < 4; i++) {
            int e = i*256 + t;
            int c16 = e & 7, row = (e >> 3) & 63, pl = e >> 9;
            const __half* src = pl ? (g_vt + ((size_t)bh*DKH + row)*SEQ + k0 + c16*8)
                                   : (g_km + ((size_t)bh*SEQ + k0 + row)*DKH + c16*8);
            cpasync16(sb + 16384 + st*16384 + pl*8192 + SWZ(row, c16), src);
        }
        asm volatile("cp.async.commit_group;" ::: "memory");
    };
    issue_kv(0, 0);

    float m0r = -1e30f, m1r = -1e30f, l0 = 0.f, l1 = 0.f;
    float oacc[8][4];
#pragma unroll
    for (int j = 0; j < 8; j++)
#pragma unroll
        for (int k = 0; k < 4; k++) oacc[j][k] = 0.f;

    for (int kt = 0; kt < 32; kt++) {
        const int st = kt & 1;
        if (kt + 1 < 32) {
            issue_kv(kt + 1, st ^ 1);
            asm volatile("cp.async.wait_group 1;" ::: "memory");
        } else {
            asm volatile("cp.async.wait_group 0;" ::: "memory");
        }
        __syncthreads();

        const uint32_t Kt = sb + 16384 + st*16384;
        const uint32_t Vt = Kt + 8192;

        float sacc[8][4];
#pragma unroll
        for (int j = 0; j < 8; j++)
#pragma unroll
            for (int k = 0; k < 4; k++) sacc[j][k] = 0.f;

#pragma unroll
        for (int ks = 0; ks < 4; ks++) {
            uint32_t a1[4];
            {
                int r = row0 + (lane & 15);
                int c16 = ks*2 + ((lane >> 4) & 1);
                ldsm4(a1, sb + SWZ(r, c16));
            }
            uint32_t bb[4][4];
            int br = (lane & 7) + ((lane >> 4) & 1) * 8;
            int bc16 = ks*2 + ((lane >> 3) & 1);
#pragma unroll
            for (int g = 0; g < 4; g++) { int rr = g*16 + br; ldsm4(bb[g], Kt + SWZ(rr, bc16)); }
#pragma unroll
            for (int j = 0; j < 8; j++) mma16816h(sacc[j], a1, &bb[j>>1][(j&1)*2]);
        }

        float mx0 = -1e30f, mx1 = -1e30f;
#pragma unroll
        for (int j = 0; j < 8; j++) {
#pragma unroll
            for (int k = 0; k < 4; k++) sacc[j][k] *= 0.125f;
            mx0 = fmaxf(mx0, fmaxf(sacc[j][0], sacc[j][1]));
            mx1 = fmaxf(mx1, fmaxf(sacc[j][2], sacc[j][3]));
        }
        mx0 = fmaxf(mx0, __shfl_xor_sync(0xffffffffu, mx0, 1));
        mx0 = fmaxf(mx0, __shfl_xor_sync(0xffffffffu, mx0, 2));
        mx1 = fmaxf(mx1, __shfl_xor_sync(0xffffffffu, mx1, 1));
        mx1 = fmaxf(mx1, __shfl_xor_sync(0xffffffffu, mx1, 2));
        float mn0 = fmaxf(m0r, mx0), mn1 = fmaxf(m1r, mx1);
        float corr0 = __expf(m0r - mn0), corr1 = __expf(m1r - mn1);
        m0r = mn0; m1r = mn1;
        float rs0 = 0.f, rs1 = 0.f;
#pragma unroll
        for (int j = 0; j < 8; j++) {
            sacc[j][0] = __expf(sacc[j][0] - mn0);
            sacc[j][1] = __expf(sacc[j][1] - mn0);
            sacc[j][2] = __expf(sacc[j][2] - mn1);
            sacc[j][3] = __expf(sacc[j][3] - mn1);
            rs0 += sacc[j][0] + sacc[j][1];
            rs1 += sacc[j][2] + sacc[j][3];
            oacc[j][0] *= corr0; oacc[j][1] *= corr0;
            oacc[j][2] *= corr1; oacc[j][3] *= corr1;
        }
        rs0 += __shfl_xor_sync(0xffffffffu, rs0, 1);
        rs0 += __shfl_xor_sync(0xffffffffu, rs0, 2);
        rs1 += __shfl_xor_sync(0xffffffffu, rs1, 1);
        rs1 += __shfl_xor_sync(0xffffffffu, rs1, 2);
        l0 = l0*corr0 + rs0;
        l1 = l1*corr1 + rs1;

        // P fragments: fp16 hi + exact residual lo
        uint32_t ph[4][4], plo[4][4];
#pragma unroll
        for (int ks = 0; ks < 4; ks++) {
            int j0 = 2*ks, j1 = 2*ks + 1;
            float p0[4] = {sacc[j0][0], sacc[j0][1], sacc[j0][2], sacc[j0][3]};
            float p1[4] = {sacc[j1][0], sacc[j1][1], sacc[j1][2], sacc[j1][3]};
            uint32_t h0 = pack2h(p0[0], p0[1]), h1 = pack2h(p0[2], p0[3]);
            uint32_t h2 = pack2h(p1[0], p1[1]), h3 = pack2h(p1[2], p1[3]);
            ph[ks][0] = h0; ph[ks][1] = h1; ph[ks][2] = h2; ph[ks][3] = h3;
            float2 f0 = __half22float2(*(__half2*)&h0);
            float2 f1 = __half22float2(*(__half2*)&h1);
            float2 f2 = __half22float2(*(__half2*)&h2);
            float2 f3 = __half22float2(*(__half2*)&h3);
            plo[ks][0] = pack2h(p0[0]-f0.x, p0[1]-f0.y);
            plo[ks][1] = pack2h(p0[2]-f1.x, p0[3]-f1.y);
            plo[ks][2] = pack2h(p1[0]-f2.x, p1[1]-f2.y);
            plo[ks][3] = pack2h(p1[2]-f3.x, p1[3]-f3.y);
        }

        // O += P V (hi + residual terms)
#pragma unroll
        for (int ks = 0; ks < 4; ks++) {
            uint32_t bb[4][4];
            int br = (lane & 7) + ((lane >> 4) & 1) * 8;
            int bc16 = ks*2 + ((lane >> 3) & 1);
#pragma unroll
            for (int g = 0; g < 4; g++) { int rr = g*16 + br; ldsm4(bb[g], Vt + SWZ(rr, bc16)); }
#pragma unroll
            for (int j = 0; j < 8; j++) mma16816h(oacc[j], ph[ks], &bb[j>>1][(j&1)*2]);
#pragma unroll
            for (int j = 0; j < 8; j++) mma16816h(oacc[j], plo[ks], &bb[j>>1][(j&1)*2]);
        }
        __syncthreads();
    }

    // epilogue: write ctx fp16 [s*B+b][h*64+dk]
    const float inv0 = 1.f / l0, inv1 = 1.f / l1;
    const int b = bh >> 4, h = bh & 15;
    const int sg = q0 + row0 + (lane >> 2);
#pragma unroll
    for (int j = 0; j < 8; j++) {
        int dk = j*8 + (lane & 3)*2;
        uint32_t w0 = pack2h(oacc[j][0]*inv0, oacc[j][1]*inv0);
        uint32_t w1 = pack2h(oacc[j][2]*inv1, oacc[j][3]*inv1);
        *(uint32_t*)&g_ctxh[((size_t)sg*BATCH + b)*DIM + h*DKH + dk] = w0;
        *(uint32_t*)&g_ctxh[((size_t)(sg+8)*BATCH + b)*DIM + h*DKH + dk] = w1;
    }
}

// ---------------- launch ----------------
extern "C" void kernel_launch(void* const* d_in, const int* in_sizes, int n_in,
                              void* d_out, int out_size) {
    const float* in5[5]  = {(const float*)d_in[0], (const float*)d_in[1], (const float*)d_in[2],
                            (const float*)d_in[3], (const float*)d_in[4]};
    const float* W6[6]   = {(const float*)d_in[5],  (const float*)d_in[7],  (const float*)d_in[9],
                            (const float*)d_in[11], (const float*)d_in[13], (const float*)d_in[15]};
    const float* bias6[6]= {(const float*)d_in[6],  (const float*)d_in[8],  (const float*)d_in[10],
                            (const float*)d_in[12], (const float*)d_in[14], (const float*)d_in[16]};
    const float* W_Vqx= (const float*)d_in[17];
    const float* b_Vqx= (const float*)d_in[18];
    const float* W_Vqc= (const float*)d_in[19];
    const float* b_Vqc= (const float*)d_in[20];
    const float* W_Vkx= (const float*)d_in[21];
    const float* b_Vkx= (const float*)d_in[22];
    const float* W_Vkc= (const float*)d_in[23];
    const float* b_Vkc= (const float*)d_in[24];

    __half *pA, *pW, *pP, *pCtx;
    cudaGetSymbolAddress((void**)&pA,   g_hA);
    cudaGetSymbolAddress((void**)&pW,   g_hW);
    cudaGetSymbolAddress((void**)&pP,   g_hP);
    cudaGetSymbolAddress((void**)&pCtx, g_ctxh);

    const size_t NA = (size_t)NROW * DIM;
    const size_t NW = (size_t)DIM * DIM;
    const int n4 = (int)(NA / 4);

    // 1) convert 5 inputs to fp16 (one batched launch)
    CvtArgs ca;
    for (int i = 0; i < 5; i++) {
        ca.in[i]  = (const float4*)in5[i];
        ca.out[i] = pA + (size_t)i * NA;
    }
    tofp16_kernel<<<dim3(n4/256, 5), 256>>>(ca, n4);

    // 2) transpose weights to fp16
    WArgs wa;
    for (int i = 0; i < 6; i++)
        wa.w[i] = { W6[i], pW + (size_t)i * NW };
    wsplit_kernel<<<dim3(32, 32, 6), dim3(32, 8)>>>(wa);

    // 3) five projections, fp16 HMMA, fp16 outputs
    cudaFuncSetAttribute(gemm_mma_kernel, cudaFuncAttributeMaxDynamicSharedMemorySize, GEMM_SMEM);
    GArgs ga;
    for (int i = 0; i < 5; i++)
        ga.g[i] = { pA + (size_t)i*NA, pW + (size_t)i*NW, bias6[i], nullptr, pP + (size_t)i*NA };
    gemm_mma_kernel<<<dim3(8, 32, 5), 256, GEMM_SMEM>>>(ga);

    // 4) lambda gates + mixing -> fp16 [bh][s][dk]; V transpose
    lam_mix_kernel<<<dim3(NROW, 2), 256>>>(W_Vqx, b_Vqx, W_Vqc, b_Vqc,
                                           W_Vkx, b_Vkx, W_Vkc, b_Vkc);
    vsplit_kernel<<<dim3(SEQ/64, BH), 256>>>();

    // 5) fp16 HMMA flash attention (6th launch -> ncu -s 5)
    cudaFuncSetAttribute(flash_mma_kernel, cudaFuncAttributeMaxDynamicSharedMemorySize, FL_SMEM);
    flash_mma_kernel<<<dim3(SEQ/128, BH), 256, FL_SMEM>>>();

    // 6) output projection straight from fp16 ctx into d_out (fp32)
    GArgs go;
    go.g[0] = { pCtx, pW + (size_t)5*NW, bias6[5], (float*)d_out, nullptr };
    go.g[1] = go.g[0]; go.g[2] = go.g[0]; go.g[3] = go.g[0]; go.g[4] = go.g[0];
    gemm_mma_kernel<<<dim3(8, 32, 1), 256, GEMM_SMEM>>>(go);
}

// round 17
// speedup vs baseline: 2.7741x; 1.0950x over previous
#include <cuda_runtime.h>
#include <cuda_bf16.h>
#include <cuda_fp16.h>
#include <math.h>
#include <stdint.h>

#define SEQ   2048
#define BATCH 2
#define DIM   1024
#define HEADS 16
#define DKH   64
#define NROW  (SEQ*BATCH)   // 4096
#define BH    (BATCH*HEADS) // 32

// ---------------- mma.sync helpers (portable sm_80+ ISA) ----------------
__device__ __forceinline__ uint32_t smem_to_u32(const void* p) {
    uint32_t a;
    asm("{ .reg .u64 t; cvta.to.shared.u64 t, %1; cvt.u32.u64 %0, t; }" : "=r"(a) : "l"(p));
    return a;
}
__device__ __forceinline__ void cpasync16(uint32_t s, const void* g) {
    asm volatile("cp.async.cg.shared.global [%0], [%1], 16;" :: "r"(s), "l"(g) : "memory");
}
__device__ __forceinline__ void ldsm4(uint32_t* r, uint32_t addr) {
    asm volatile("ldmatrix.sync.aligned.m8n8.x4.shared.b16 {%0,%1,%2,%3}, [%4];"
        : "=r"(r[0]), "=r"(r[1]), "=r"(r[2]), "=r"(r[3]) : "r"(addr));
}
__device__ __forceinline__ void mma16816h(float* d, const uint32_t* a, const uint32_t* b) {
    asm volatile("mma.sync.aligned.m16n8k16.row.col.f32.f16.f16.f32 "
        "{%0,%1,%2,%3}, {%4,%5,%6,%7}, {%8,%9}, {%0,%1,%2,%3};"
        : "+f"(d[0]), "+f"(d[1]), "+f"(d[2]), "+f"(d[3])
        : "r"(a[0]), "r"(a[1]), "r"(a[2]), "r"(a[3]), "r"(b[0]), "r"(b[1]));
}
// pack (lo, hi) into f16x2 (lo -> low half)
__device__ __forceinline__ uint32_t pack2h(float lo, float hi) {
    uint32_t r; asm("cvt.rn.f16x2.f32 %0, %1, %2;" : "=r"(r) : "f"(hi), "f"(lo)); return r;
}

#define SWZ(row, c16) ((row)*128 + ((((c16) ^ ((row)&7)))<<4))

// ---------------- scratch (device globals; no allocation allowed) ----------------
__device__ __half g_hA[5*NROW*DIM];     // 5 inputs, fp16
__device__ __half g_hW[6*DIM*DIM];      // 6 weights (transposed), fp16
__device__ __half g_hP[5*NROW*DIM];     // 5 projection outputs, fp16
__device__ __half g_ctxh[NROW*DIM];     // attention output, fp16
__device__ __half g_qm[BH*SEQ*DKH];     // mixed q, [bh][s][dk]
__device__ __half g_km[BH*SEQ*DKH];     // mixed k
__device__ __half g_vt[BH*DKH*SEQ];     // v transposed, [bh][dk][s]

// ================= tofp16: batched fp32 -> fp16 for the 5 inputs =================
struct CvtArgs { const float4* in[5]; __half* out[5]; };
__global__ __launch_bounds__(256)
void tofp16_kernel(CvtArgs a, int n4) {
    int i = blockIdx.x * blockDim.x + threadIdx.x;
    if (i >= n4) return;
    const float4* in = a.in[blockIdx.y];
    __half* out = a.out[blockIdx.y];
    float4 v = in[i];
    union { __half h[4]; uint2 u; } p;
    p.h[0] = __float2half_rn(v.x); p.h[1] = __float2half_rn(v.y);
    p.h[2] = __float2half_rn(v.z); p.h[3] = __float2half_rn(v.w);
    *(uint2*)(out + 4*(size_t)i) = p.u;
}

// ================= weight transpose -> fp16: W[K,N] -> WT[N,K] =================
struct WArg  { const float* W; __half* o; };
struct WArgs { WArg w[6]; };
__global__ __launch_bounds__(256)
void wsplit_kernel(WArgs a) {
    __shared__ float tile[32][33];
    WArg wa = a.w[blockIdx.z];
    int tx = threadIdx.x, ty = threadIdx.y;
    int x = blockIdx.x * 32 + tx;
    int yb = blockIdx.y * 32;
#pragma unroll
    for (int j = 0; j < 32; j += 8)
        tile[ty + j][tx] = wa.W[(size_t)(yb + ty + j) * DIM + x];
    __syncthreads();
    int xo = blockIdx.y * 32 + tx;
    int yo = blockIdx.x * 32;
#pragma unroll
    for (int j = 0; j < 32; j += 8)
        wa.o[(size_t)(yo + ty + j) * DIM + xo] = __float2half_rn(tile[tx][ty + j]);
}

// ================= fp16 HMMA GEMM: C = A @ W^T + bias (fp32 or fp16 out) =================
#define GBK 64
#define TILE_B 16384
#define GSTAGE_B (2*TILE_B)          // 32768
#define GSTAGES 4
#define GEMM_SMEM (GSTAGES*GSTAGE_B) // 131072
#define GNCH 16

struct GArg  { const __half* A; const __half* B; const float* bias; float* C32; __half* C16; };
struct GArgs { GArg g[5]; };

__global__ __launch_bounds__(256, 1)
void gemm_mma_kernel(GArgs args) {
    extern __shared__ char smem[];
    const uint32_t sb = smem_to_u32(smem);
    GArg ga = args.g[blockIdx.z];
    const int t = threadIdx.x;
    const int wid = t >> 5, lane = t & 31;
    const int wm = wid & 3, wn = wid >> 2;
    const int m0 = blockIdx.y * 128, n0 = blockIdx.x * 128;

    float acc[2][8][4];
#pragma unroll
    for (int i = 0; i < 2; i++)
#pragma unroll
        for (int j = 0; j < 8; j++)
#pragma unroll
            for (int k = 0; k < 4; k++) acc[i][j][k] = 0.f;

    auto issue = [&](int c) {
        const int kc = c * GBK;
        const uint32_t st = sb + (c & (GSTAGES-1)) * GSTAGE_B;
#pragma unroll
        for (int i = 0; i < 4; i++) {
            int e = i * 256 + t;
            int c16 = e & 7, row = e >> 3;
            cpasync16(st + SWZ(row, c16),
                      ga.A + (size_t)(m0 + row) * DIM + kc + c16 * 8);
        }
#pragma unroll
        for (int i = 0; i < 4; i++) {
            int e = i * 256 + t;
            int c16 = e & 7, row = e >> 3;
            cpasync16(st + TILE_B + SWZ(row, c16),
                      ga.B + (size_t)(n0 + row) * DIM + kc + c16 * 8);
        }
        asm volatile("cp.async.commit_group;" ::: "memory");
    };

    issue(0); issue(1); issue(2);

    for (int c = 0; c < GNCH; c++) {
        if (c + 3 < GNCH) {
            issue(c + 3);
            asm volatile("cp.async.wait_group 3;" ::: "memory");
        } else if (c + 2 < GNCH) {
            asm volatile("cp.async.wait_group 2;" ::: "memory");
        } else if (c + 1 < GNCH) {
            asm volatile("cp.async.wait_group 1;" ::: "memory");
        } else {
            asm volatile("cp.async.wait_group 0;" ::: "memory");
        }
        __syncthreads();

        const uint32_t At = sb + (c & (GSTAGES-1)) * GSTAGE_B;
        const uint32_t Bt = At + TILE_B;
#pragma unroll
        for (int ks = 0; ks < 4; ks++) {
            uint32_t af[2][4];
            {
                int ar = wm*32 + (lane & 15);
                int ac16 = ks*2 + ((lane >> 4) & 1);
                ldsm4(af[0], At + SWZ(ar,      ac16));
                ldsm4(af[1], At + SWZ(ar + 16, ac16));
            }
            uint32_t bb[4][4];
            {
                int br = (lane & 7) + ((lane >> 4) & 1) * 8;
                int bc16 = ks*2 + ((lane >> 3) & 1);
#pragma unroll
                for (int g = 0; g < 4; g++)
                    ldsm4(bb[g], Bt + SWZ(wn*64 + g*16 + br, bc16));
            }
#pragma unroll
            for (int tm = 0; tm < 2; tm++)
#pragma unroll
                for (int tn = 0; tn < 8; tn++)
                    mma16816h(acc[tm][tn], af[tm], &bb[tn >> 1][(tn & 1) * 2]);
        }
        __syncthreads();
    }

#pragma unroll
    for (int tm = 0; tm < 2; tm++) {
        int r0 = m0 + wm*32 + tm*16 + lane / 4;
#pragma unroll
        for (int tn = 0; tn < 8; tn++) {
            int cc = n0 + wn*64 + tn*8 + (lane % 4) * 2;
            float2 bv = *(const float2*)&ga.bias[cc];
            float a0 = acc[tm][tn][0] + bv.x, a1 = acc[tm][tn][1] + bv.y;
            float a2 = acc[tm][tn][2] + bv.x, a3 = acc[tm][tn][3] + bv.y;
            if (ga.C16) {
                *(uint32_t*)&ga.C16[(size_t)r0 * DIM + cc]       = pack2h(a0, a1);
                *(uint32_t*)&ga.C16[(size_t)(r0 + 8) * DIM + cc] = pack2h(a2, a3);
            } else {
                *(float2*)&ga.C32[(size_t)r0 * DIM + cc]       = make_float2(a0, a1);
                *(float2*)&ga.C32[(size_t)(r0 + 8) * DIM + cc] = make_float2(a2, a3);
            }
        }
    }
}

// ---------------- lambda gate + mix (fp16 in) -> fp16 [bh][s][dk] ----------------
__global__ __launch_bounds__(256)
void lam_mix_kernel(const float* __restrict__ Wvqx, const float* __restrict__ bvqx,
                    const float* __restrict__ Wvqc, const float* __restrict__ bvqc,
                    const float* __restrict__ Wvkx, const float* __restrict__ bvkx,
                    const float* __restrict__ Wvkc, const float* __restrict__ bvkc) {
    const int r   = blockIdx.x;
    const bool isK = (blockIdx.y != 0);
    const __half* a = g_hP + (isK ? 1 : 0) * (size_t)NROW * DIM;
    const __half* c = g_hP + (isK ? 4 : 3) * (size_t)NROW * DIM;
    const float* Wa = isK ? Wvkx : Wvqx;
    const float* Wc = isK ? Wvkc : Wvqc;
    const float bsum = isK ? (bvkx[0] + bvkc[0]) : (bvqx[0] + bvqc[0]);
    __half* om = isK ? g_km : g_qm;

    const int t = threadIdx.x, lane = t & 31, w = t >> 5;
    const int s = r >> 1, b = r & 1;
    const int d0 = t * 4;
    float av[4], cv[4];
    {
        union { uint2 u; __half h[4]; } ua, uc;
        ua.u = *(const uint2*)&a[(size_t)r*1024 + d0];
        uc.u = *(const uint2*)&c[(size_t)r*1024 + d0];
#pragma unroll
        for (int i = 0; i < 4; i++) { av[i] = __half2float(ua.h[i]); cv[i] = __half2float(uc.h[i]); }
    }
    float part = 0.f;
#pragma unroll
    for (int i = 0; i < 4; i++)
        part += av[i]*Wa[d0+i] + cv[i]*Wc[d0+i];
    // warp shuffle reduce, then one 8-word smem stage
    part += __shfl_xor_sync(0xffffffffu, part, 16);
    part += __shfl_xor_sync(0xffffffffu, part, 8);
    part += __shfl_xor_sync(0xffffffffu, part, 4);
    part += __shfl_xor_sync(0xffffffffu, part, 2);
    part += __shfl_xor_sync(0xffffffffu, part, 1);
    __shared__ float red[8];
    if (lane == 0) red[w] = part;
    __syncthreads();
    float tot = red[0] + red[1] + red[2] + red[3] + red[4] + red[5] + red[6] + red[7];
    float lam = 1.f / (1.f + __expf(-(tot + bsum)));
    const int hh = d0 >> 6, dk = d0 & 63;
    union { uint2 u; __half h[4]; } out;
#pragma unroll
    for (int i = 0; i < 4; i++)
        out.h[i] = __float2half_rn(av[i] + lam*(cv[i] - av[i]));
    *(uint2*)&om[((size_t)(b*HEADS + hh)*SEQ + s)*DKH + dk] = out.u;
}

// ---------------- V transpose: g_hP[vx] -> g_vt [bh][dk][s] ----------------
__global__ __launch_bounds__(256)
void vsplit_kernel() {
    __shared__ float tile[64][65];
    const int t = threadIdx.x;
    const int s0 = blockIdx.x * 64, bh = blockIdx.y;
    const int b = bh >> 4, h = bh & 15;
    const __half* v = g_hP + 2 * (size_t)NROW * DIM;
#pragma unroll
    for (int i = 0; i < 4; i++) {
        int e = i*256 + t;
        int sr = e >> 4, c4 = e & 15;
        union { uint2 u; __half h[4]; } uv;
        uv.u = *(const uint2*)&v[((size_t)(s0+sr)*BATCH + b)*DIM + h*DKH + c4*4];
#pragma unroll
        for (int k = 0; k < 4; k++) tile[sr][c4*4+k] = __half2float(uv.h[k]);
    }
    __syncthreads();
    const int dkr = t >> 2, sc = (t & 3) * 16;
    union { __half h[8]; uint4 u; } hp[2];
#pragma unroll
    for (int ch = 0; ch < 2; ch++)
#pragma unroll
        for (int k = 0; k < 8; k++)
            hp[ch].h[k] = __float2half_rn(tile[sc + ch*8 + k][dkr]);
    size_t off = ((size_t)bh*DKH + dkr)*SEQ + s0 + sc;
    *(uint4*)&g_vt[off] = hp[0].u; *(uint4*)&g_vt[off+8] = hp[1].u;
}

// ---------------- fp16 HMMA flash attention ----------------
// Q 16KB | 2 stages x {K 8KB | V 8KB}; QK 1 term, PV 1 term; Q frags hoisted.
#define FL_SMEM (16384 + 2*16384)

__global__ __launch_bounds__(256)
void flash_mma_kernel() {
    extern __shared__ char fsm[];
    const uint32_t sb = smem_to_u32(fsm);
    const int t = threadIdx.x, lane = t & 31, w = t >> 5;
    const int q0 = blockIdx.x * 128, bh = blockIdx.y;
    const int row0 = w * 16;

    {
        size_t qoff = ((size_t)bh*SEQ + q0)*DKH;
#pragma unroll
        for (int i = 0; i < 4; i++) {
            int e = i*256 + t;
            int c16 = e & 7, row = e >> 3;
            cpasync16(sb + SWZ(row, c16), g_qm + qoff + row*DKH + c16*8);
        }
        asm volatile("cp.async.commit_group;" ::: "memory");
    }
    auto issue_kv = [&](int kt, int st) {
        int k0 = kt * 64;
#pragma unroll
        for (int i = 0; i < 4; i++) {
            int e = i*256 + t;
            int c16 = e & 7, row = (e >> 3) & 63, pl = e >> 9;
            const __half* src = pl ? (g_vt + ((size_t)bh*DKH + row)*SEQ + k0 + c16*8)
                                   : (g_km + ((size_t)bh*SEQ + k0 + row)*DKH + c16*8);
            cpasync16(sb + 16384 + st*16384 + pl*8192 + SWZ(row, c16), src);
        }
        asm volatile("cp.async.commit_group;" ::: "memory");
    };
    issue_kv(0, 0);

    // wait for Q (1 pending group = kv0), then hoist Q fragments into registers
    asm volatile("cp.async.wait_group 1;" ::: "memory");
    __syncthreads();
    uint32_t qf[4][4];
#pragma unroll
    for (int ks = 0; ks < 4; ks++) {
        int r = row0 + (lane & 15);
        int c16 = ks*2 + ((lane >> 4) & 1);
        ldsm4(qf[ks], sb + SWZ(r, c16));
    }

    float m0r = -1e30f, m1r = -1e30f, l0 = 0.f, l1 = 0.f;
    float oacc[8][4];
#pragma unroll
    for (int j = 0; j < 8; j++)
#pragma unroll
        for (int k = 0; k < 4; k++) oacc[j][k] = 0.f;

    for (int kt = 0; kt < 32; kt++) {
        const int st = kt & 1;
        if (kt + 1 < 32) {
            issue_kv(kt + 1, st ^ 1);
            asm volatile("cp.async.wait_group 1;" ::: "memory");
        } else {
            asm volatile("cp.async.wait_group 0;" ::: "memory");
        }
        __syncthreads();

        const uint32_t Kt = sb + 16384 + st*16384;
        const uint32_t Vt = Kt + 8192;

        float sacc[8][4];
#pragma unroll
        for (int j = 0; j < 8; j++)
#pragma unroll
            for (int k = 0; k < 4; k++) sacc[j][k] = 0.f;

#pragma unroll
        for (int ks = 0; ks < 4; ks++) {
            uint32_t bb[4][4];
            int br = (lane & 7) + ((lane >> 4) & 1) * 8;
            int bc16 = ks*2 + ((lane >> 3) & 1);
#pragma unroll
            for (int g = 0; g < 4; g++) { int rr = g*16 + br; ldsm4(bb[g], Kt + SWZ(rr, bc16)); }
#pragma unroll
            for (int j = 0; j < 8; j++) mma16816h(sacc[j], qf[ks], &bb[j>>1][(j&1)*2]);
        }

        float mx0 = -1e30f, mx1 = -1e30f;
#pragma unroll
        for (int j = 0; j < 8; j++) {
#pragma unroll
            for (int k = 0; k < 4; k++) sacc[j][k] *= 0.125f;
            mx0 = fmaxf(mx0, fmaxf(sacc[j][0], sacc[j][1]));
            mx1 = fmaxf(mx1, fmaxf(sacc[j][2], sacc[j][3]));
        }
        mx0 = fmaxf(mx0, __shfl_xor_sync(0xffffffffu, mx0, 1));
        mx0 = fmaxf(mx0, __shfl_xor_sync(0xffffffffu, mx0, 2));
        mx1 = fmaxf(mx1, __shfl_xor_sync(0xffffffffu, mx1, 1));
        mx1 = fmaxf(mx1, __shfl_xor_sync(0xffffffffu, mx1, 2));
        float mn0 = fmaxf(m0r, mx0), mn1 = fmaxf(m1r, mx1);
        float corr0 = __expf(m0r - mn0), corr1 = __expf(m1r - mn1);
        m0r = mn0; m1r = mn1;
        float rs0 = 0.f, rs1 = 0.f;
#pragma unroll
        for (int j = 0; j < 8; j++) {
            sacc[j][0] = __expf(sacc[j][0] - mn0);
            sacc[j][1] = __expf(sacc[j][1] - mn0);
            sacc[j][2] = __expf(sacc[j][2] - mn1);
            sacc[j][3] = __expf(sacc[j][3] - mn1);
            rs0 += sacc[j][0] + sacc[j][1];
            rs1 += sacc[j][2] + sacc[j][3];
            oacc[j][0] *= corr0; oacc[j][1] *= corr0;
            oacc[j][2] *= corr1; oacc[j][3] *= corr1;
        }
        rs0 += __shfl_xor_sync(0xffffffffu, rs0, 1);
        rs0 += __shfl_xor_sync(0xffffffffu, rs0, 2);
        rs1 += __shfl_xor_sync(0xffffffffu, rs1, 1);
        rs1 += __shfl_xor_sync(0xffffffffu, rs1, 2);
        l0 = l0*corr0 + rs0;
        l1 = l1*corr1 + rs1;

        // P fragments (fp16, single term)
        uint32_t ph[4][4];
#pragma unroll
        for (int ks = 0; ks < 4; ks++) {
            int j0 = 2*ks, j1 = 2*ks + 1;
            ph[ks][0] = pack2h(sacc[j0][0], sacc[j0][1]);
            ph[ks][1] = pack2h(sacc[j0][2], sacc[j0][3]);
            ph[ks][2] = pack2h(sacc[j1][0], sacc[j1][1]);
            ph[ks][3] = pack2h(sacc[j1][2], sacc[j1][3]);
        }

        // O += P V
#pragma unroll
        for (int ks = 0; ks < 4; ks++) {
            uint32_t bb[4][4];
            int br = (lane & 7) + ((lane >> 4) & 1) * 8;
            int bc16 = ks*2 + ((lane >> 3) & 1);
#pragma unroll
            for (int g = 0; g < 4; g++) { int rr = g*16 + br; ldsm4(bb[g], Vt + SWZ(rr, bc16)); }
#pragma unroll
            for (int j = 0; j < 8; j++) mma16816h(oacc[j], ph[ks], &bb[j>>1][(j&1)*2]);
        }
        __syncthreads();
    }

    // epilogue: write ctx fp16 [s*B+b][h*64+dk]
    const float inv0 = 1.f / l0, inv1 = 1.f / l1;
    const int b = bh >> 4, h = bh & 15;
    const int sg = q0 + row0 + (lane >> 2);
#pragma unroll
    for (int j = 0; j < 8; j++) {
        int dk = j*8 + (lane & 3)*2;
        uint32_t w0 = pack2h(oacc[j][0]*inv0, oacc[j][1]*inv0);
        uint32_t w1 = pack2h(oacc[j][2]*inv1, oacc[j][3]*inv1);
        *(uint32_t*)&g_ctxh[((size_t)sg*BATCH + b)*DIM + h*DKH + dk] = w0;
        *(uint32_t*)&g_ctxh[((size_t)(sg+8)*BATCH + b)*DIM + h*DKH + dk] = w1;
    }
}

// ---------------- launch ----------------
extern "C" void kernel_launch(void* const* d_in, const int* in_sizes, int n_in,
                              void* d_out, int out_size) {
    const float* in5[5]  = {(const float*)d_in[0], (const float*)d_in[1], (const float*)d_in[2],
                            (const float*)d_in[3], (const float*)d_in[4]};
    const float* W6[6]   = {(const float*)d_in[5],  (const float*)d_in[7],  (const float*)d_in[9],
                            (const float*)d_in[11], (const float*)d_in[13], (const float*)d_in[15]};
    const float* bias6[6]= {(const float*)d_in[6],  (const float*)d_in[8],  (const float*)d_in[10],
                            (const float*)d_in[12], (const float*)d_in[14], (const float*)d_in[16]};
    const float* W_Vqx= (const float*)d_in[17];
    const float* b_Vqx= (const float*)d_in[18];
    const float* W_Vqc= (const float*)d_in[19];
    const float* b_Vqc= (const float*)d_in[20];
    const float* W_Vkx= (const float*)d_in[21];
    const float* b_Vkx= (const float*)d_in[22];
    const float* W_Vkc= (const float*)d_in[23];
    const float* b_Vkc= (const float*)d_in[24];

    __half *pA, *pW, *pP, *pCtx;
    cudaGetSymbolAddress((void**)&pA,   g_hA);
    cudaGetSymbolAddress((void**)&pW,   g_hW);
    cudaGetSymbolAddress((void**)&pP,   g_hP);
    cudaGetSymbolAddress((void**)&pCtx, g_ctxh);

    const size_t NA = (size_t)NROW * DIM;
    const size_t NW = (size_t)DIM * DIM;
    const int n4 = (int)(NA / 4);

    // 1) convert 5 inputs to fp16 (one batched launch)
    CvtArgs ca;
    for (int i = 0; i < 5; i++) {
        ca.in[i]  = (const float4*)in5[i];
        ca.out[i] = pA + (size_t)i * NA;
    }
    tofp16_kernel<<<dim3(n4/256, 5), 256>>>(ca, n4);

    // 2) transpose weights to fp16
    WArgs wa;
    for (int i = 0; i < 6; i++)
        wa.w[i] = { W6[i], pW + (size_t)i * NW };
    wsplit_kernel<<<dim3(32, 32, 6), dim3(32, 8)>>>(wa);

    // 3) five projections, fp16 HMMA, fp16 outputs
    cudaFuncSetAttribute(gemm_mma_kernel, cudaFuncAttributeMaxDynamicSharedMemorySize, GEMM_SMEM);
    GArgs ga;
    for (int i = 0; i < 5; i++)
        ga.g[i] = { pA + (size_t)i*NA, pW + (size_t)i*NW, bias6[i], nullptr, pP + (size_t)i*NA };
    gemm_mma_kernel<<<dim3(8, 32, 5), 256, GEMM_SMEM>>>(ga);

    // 4) lambda gates + mixing -> fp16 [bh][s][dk]; V transpose
    lam_mix_kernel<<<dim3(NROW, 2), 256>>>(W_Vqx, b_Vqx, W_Vqc, b_Vqc,
                                           W_Vkx, b_Vkx, W_Vkc, b_Vkc);
    vsplit_kernel<<<dim3(SEQ/64, BH), 256>>>();

    // 5) fp16 HMMA flash attention (6th launch -> ncu -s 5)
    cudaFuncSetAttribute(flash_mma_kernel, cudaFuncAttributeMaxDynamicSharedMemorySize, FL_SMEM);
    flash_mma_kernel<<<dim3(SEQ/128, BH), 256, FL_SMEM>>>();

    // 6) output projection straight from fp16 ctx into d_out (fp32)
    GArgs go;
    go.g[0] = { pCtx, pW + (size_t)5*NW, bias6[5], (float*)d_out, nullptr };
    go.g[1] = go.g[0]; go.g[2] = go.g[0]; go.g[3] = go.g[0]; go.g[4] = go.g[0];
    gemm_mma_kernel<<<dim3(8, 32, 1), 256, GEMM_SMEM>>>(go);
}